// round 2
// baseline (speedup 1.0000x reference)
#include <cuda_runtime.h>
#include <math.h>

#define BB 16
#define SEQL 1025
#define EMB 384
#define HDS 6
#define HD 64
#define NF 32
#define ROWS (BB*SEQL)

// ---------------- scratch (static device globals; no allocations) ----------
__device__ float g_q[(size_t)BB*HDS*SEQL*HD];      // [b,h,s,d]
__device__ float g_k[(size_t)BB*HDS*SEQL*HD];
__device__ float g_v[(size_t)BB*HDS*SEQL*HD];
__device__ float g_ao[(size_t)ROWS*EMB];           // [b,s,e] attn output
__device__ float g_cos[SEQL*HDS*NF];
__device__ float g_sin[SEQL*HDS*NF];
__device__ float g_freqs[HDS*NF*2];

// ---------------- XLA erfinv (f32 polynomial, Giles) ------------------------
__device__ __forceinline__ float erfinv_xla(float x) {
    float w = -log1pf(-__fmul_rn(x, x));
    float p;
    if (w < 5.0f) {
        w = w - 2.5f;
        p = 2.81022636e-08f;
        p = fmaf(p, w, 3.43273939e-07f);
        p = fmaf(p, w, -3.5233877e-06f);
        p = fmaf(p, w, -4.39150654e-06f);
        p = fmaf(p, w, 0.00021858087f);
        p = fmaf(p, w, -0.00125372503f);
        p = fmaf(p, w, -0.00417768164f);
        p = fmaf(p, w, 0.246640727f);
        p = fmaf(p, w, 1.50140941f);
    } else {
        w = sqrtf(w) - 3.0f;
        p = -0.000200214257f;
        p = fmaf(p, w, 0.000100950558f);
        p = fmaf(p, w, 0.00134934322f);
        p = fmaf(p, w, -0.00367342844f);
        p = fmaf(p, w, 0.00573950773f);
        p = fmaf(p, w, -0.0076224613f);
        p = fmaf(p, w, 0.00943887047f);
        p = fmaf(p, w, 1.00167406f);
        p = fmaf(p, w, 2.83297682f);
    }
    return p * x;
}

__global__ void init_freqs(float inv_g) {
    int n = threadIdx.x;                      // 0..191 : n = h*32 + f
    if (n >= HDS * NF) return;
    float alpha0 = powf(inv_g, 1.0f);
    float alpha1 = powf(inv_g, 2.0f);
    float fi = (float)(n + 1);
    float z0 = fmodf(__fmul_rn(fi, alpha0), 1.0f);
    float z1 = fmodf(__fmul_rn(fi, alpha1), 1.0f);
    float d0 = erfinv_xla(__fmul_rn(2.0f, z0) - 1.0f);
    float d1 = erfinv_xla(__fmul_rn(2.0f, z1) - 1.0f);
    float nrm = sqrtf(__fadd_rn(__fmul_rn(d0, d0), __fmul_rn(d1, d1)));
    d0 = __fdiv_rn(d0, nrm);
    d1 = __fdiv_rn(d1, nrm);
    int f = n % NF;
    float t = __fmul_rn((float)f, (1.0f / 31.0f));     // linspace(0,1,32)
    float omega = __fmul_rn(0.1f, powf(10000.0f, t));
    g_freqs[n * 2 + 0] = __fmul_rn(d0, omega);
    g_freqs[n * 2 + 1] = __fmul_rn(d1, omega);
}

__global__ void init_trig() {
    int idx = blockIdx.x * blockDim.x + threadIdx.x;
    if (idx >= SEQL * HDS * NF) return;
    int s = idx / (HDS * NF);
    int r = idx % (HDS * NF);
    float c0 = 0.f, c1 = 0.f;
    if (s > 0) {
        int p = s - 1;
        int xi = p % 32, yi = p / 32;
        c0 = __fmul_rn(__fdiv_rn((float)xi, 31.0f), 2.0f) - 1.0f;
        c1 = __fmul_rn(__fdiv_rn((float)yi, 31.0f), 2.0f) - 1.0f;
    }
    float f0 = g_freqs[r * 2 + 0];
    float f1 = g_freqs[r * 2 + 1];
    float th = __fadd_rn(__fmul_rn(f0, c0), __fmul_rn(f1, c1));
    g_cos[idx] = cosf(th);
    g_sin[idx] = sinf(th);
}

// ---------------- QKV projection + fused RoPE -------------------------------
// grid: (257 row-blocks, 6 heads, 3 matrices), block 256.
// 64x64 output tile, K-chunks of 32. Thread (tr,tc) owns rows 4tr+i and the
// RoPE-paired columns {2tc, 2tc+1, 2tc+32, 2tc+33}.
__global__ void __launch_bounds__(256) qkv_kernel(
    const float* __restrict__ x, const float* __restrict__ Wq,
    const float* __restrict__ Wk, const float* __restrict__ Wv)
{
    int rb = blockIdx.x, h = blockIdx.y, z = blockIdx.z;
    const float* W = (z == 0) ? Wq : ((z == 1) ? Wk : Wv);
    float* outb = (z == 0) ? g_q : ((z == 1) ? g_k : g_v);

    __shared__ float xs[64][33];
    __shared__ float ws[32][64];

    int tid = threadIdx.x;
    int tr = tid >> 4, tc = tid & 15;
    float acc[4][4] = {};
    int row0 = rb * 64;

    for (int k0 = 0; k0 < EMB; k0 += 32) {
#pragma unroll
        for (int u = 0; u < 8; u++) {
            int e = tid + 256 * u;
            int rr = e >> 5, kk = e & 31;
            int gr = row0 + rr;
            xs[rr][kk] = (gr < ROWS) ? x[(size_t)gr * EMB + k0 + kk] : 0.f;
        }
#pragma unroll
        for (int u = 0; u < 8; u++) {
            int e = tid + 256 * u;
            int kk = e >> 6, cc = e & 63;
            ws[kk][cc] = W[(size_t)(k0 + kk) * EMB + h * 64 + cc];
        }
        __syncthreads();
#pragma unroll
        for (int kk = 0; kk < 32; kk++) {
            float ra[4], rbv[4];
#pragma unroll
            for (int i = 0; i < 4; i++) ra[i] = xs[tr * 4 + i][kk];
            rbv[0] = ws[kk][2 * tc];
            rbv[1] = ws[kk][2 * tc + 1];
            rbv[2] = ws[kk][2 * tc + 32];
            rbv[3] = ws[kk][2 * tc + 33];
#pragma unroll
            for (int i = 0; i < 4; i++)
#pragma unroll
                for (int j = 0; j < 4; j++)
                    acc[i][j] = fmaf(ra[i], rbv[j], acc[i][j]);
        }
        __syncthreads();
    }

#pragma unroll
    for (int i = 0; i < 4; i++) {
        int gr = row0 + tr * 4 + i;
        if (gr >= ROWS) continue;
        int b = gr / SEQL, s = gr % SEQL;
        float* dst = outb + ((size_t)(b * HDS + h) * SEQL + s) * HD;
        if (z < 2) {
#pragma unroll
            for (int j = 0; j < 2; j++) {
                int f = 2 * tc + j;
                float cv = g_cos[(s * HDS + h) * NF + f];
                float sv = g_sin[(s * HDS + h) * NF + f];
                float lo = acc[i][j], hi = acc[i][j + 2];
                dst[f]      = lo * cv - hi * sv;
                dst[f + 32] = lo * sv + hi * cv;
            }
        } else {
            dst[2 * tc]      = acc[i][0];
            dst[2 * tc + 1]  = acc[i][1];
            dst[2 * tc + 32] = acc[i][2];
            dst[2 * tc + 33] = acc[i][3];
        }
    }
}

// ---------------- Flash attention (fp32, BM=BN=64) --------------------------
__global__ void __launch_bounds__(256) attn_kernel() {
    extern __shared__ float sm[];
    float (*Qs)[65] = (float(*)[65])sm;
    float (*Ks)[65] = (float(*)[65])(sm + 64 * 65);
    float (*Vs)[65] = (float(*)[65])(sm + 2 * 64 * 65);
    float (*Ps)[65] = (float(*)[65])(sm + 3 * 64 * 65);

    int qb = blockIdx.x;     // 0..16
    int bh = blockIdx.y;     // 0..95 (= b*6 + h)
    const float* Q = g_q + (size_t)bh * SEQL * HD;
    const float* K = g_k + (size_t)bh * SEQL * HD;
    const float* V = g_v + (size_t)bh * SEQL * HD;

    int tid = threadIdx.x, tr = tid >> 4, tc = tid & 15;

#pragma unroll
    for (int u = 0; u < 16; u++) {
        int e = tid + 256 * u;
        int rr = e >> 6, dd = e & 63;
        int s = qb * 64 + rr;
        Qs[rr][dd] = (s < SEQL) ? Q[(size_t)s * HD + dd] : 0.f;
    }

    float o[4][4] = {};
    float m[4] = {-INFINITY, -INFINITY, -INFINITY, -INFINITY};
    float l[4] = {};

    for (int t = 0; t < 17; t++) {
        __syncthreads();
#pragma unroll
        for (int u = 0; u < 16; u++) {
            int e = tid + 256 * u;
            int rr = e >> 6, dd = e & 63;
            int s = t * 64 + rr;
            bool ok = (s < SEQL);
            Ks[rr][dd] = ok ? K[(size_t)s * HD + dd] : 0.f;
            Vs[rr][dd] = ok ? V[(size_t)s * HD + dd] : 0.f;
        }
        __syncthreads();

        float sacc[4][4] = {};
#pragma unroll
        for (int dd = 0; dd < 64; dd++) {
            float ra[4], rb2[4];
#pragma unroll
            for (int i = 0; i < 4; i++) ra[i] = Qs[tr * 4 + i][dd];
#pragma unroll
            for (int j = 0; j < 4; j++) rb2[j] = Ks[tc * 4 + j][dd];
#pragma unroll
            for (int i = 0; i < 4; i++)
#pragma unroll
                for (int j = 0; j < 4; j++)
                    sacc[i][j] = fmaf(ra[i], rb2[j], sacc[i][j]);
        }

#pragma unroll
        for (int i = 0; i < 4; i++)
#pragma unroll
            for (int j = 0; j < 4; j++) {
                int col = t * 64 + tc * 4 + j;
                sacc[i][j] = (col < SEQL) ? sacc[i][j] * 0.125f : -INFINITY;
            }

#pragma unroll
        for (int i = 0; i < 4; i++) {
            float rm = fmaxf(fmaxf(sacc[i][0], sacc[i][1]),
                             fmaxf(sacc[i][2], sacc[i][3]));
#pragma unroll
            for (int off = 1; off < 16; off <<= 1)
                rm = fmaxf(rm, __shfl_xor_sync(0xffffffffu, rm, off));
            float mn = fmaxf(m[i], rm);
            float corr = __expf(m[i] - mn);
            float pv[4];
            float rs = 0.f;
#pragma unroll
            for (int j = 0; j < 4; j++) {
                pv[j] = __expf(sacc[i][j] - mn);
                rs += pv[j];
            }
#pragma unroll
            for (int off = 1; off < 16; off <<= 1)
                rs += __shfl_xor_sync(0xffffffffu, rs, off);
            l[i] = l[i] * corr + rs;
            m[i] = mn;
#pragma unroll
            for (int j = 0; j < 4; j++) {
                o[i][j] *= corr;
                Ps[tr * 4 + i][tc * 4 + j] = pv[j];
            }
        }
        __syncthreads();

#pragma unroll
        for (int kk = 0; kk < 64; kk++) {
            float ra[4], rb2[4];
#pragma unroll
            for (int i = 0; i < 4; i++) ra[i] = Ps[tr * 4 + i][kk];
#pragma unroll
            for (int j = 0; j < 4; j++) rb2[j] = Vs[kk][tc * 4 + j];
#pragma unroll
            for (int i = 0; i < 4; i++)
#pragma unroll
                for (int j = 0; j < 4; j++)
                    o[i][j] = fmaf(ra[i], rb2[j], o[i][j]);
        }
    }

    int b = bh / HDS, h = bh % HDS;
#pragma unroll
    for (int i = 0; i < 4; i++) {
        int s = qb * 64 + tr * 4 + i;
        if (s >= SEQL) continue;
        float inv = 1.0f / l[i];
        float* dst = g_ao + ((size_t)(b * SEQL + s)) * EMB + h * HD;
#pragma unroll
        for (int j = 0; j < 4; j++) dst[tc * 4 + j] = o[i][j] * inv;
    }
}

// ---------------- Output projection + bias ----------------------------------
__global__ void __launch_bounds__(256) proj_kernel(
    const float* __restrict__ Wo, const float* __restrict__ bo,
    float* __restrict__ out)
{
    int rb = blockIdx.x, cb = blockIdx.y;

    __shared__ float xs[64][33];
    __shared__ float ws[32][64];

    int tid = threadIdx.x;
    int tr = tid >> 4, tc = tid & 15;
    float acc[4][4] = {};
    int row0 = rb * 64;

    for (int k0 = 0; k0 < EMB; k0 += 32) {
#pragma unroll
        for (int u = 0; u < 8; u++) {
            int e = tid + 256 * u;
            int rr = e >> 5, kk = e & 31;
            int gr = row0 + rr;
            xs[rr][kk] = (gr < ROWS) ? g_ao[(size_t)gr * EMB + k0 + kk] : 0.f;
        }
#pragma unroll
        for (int u = 0; u < 8; u++) {
            int e = tid + 256 * u;
            int kk = e >> 6, cc = e & 63;
            ws[kk][cc] = Wo[(size_t)(k0 + kk) * EMB + cb * 64 + cc];
        }
        __syncthreads();
#pragma unroll
        for (int kk = 0; kk < 32; kk++) {
            float ra[4], rbv[4];
#pragma unroll
            for (int i = 0; i < 4; i++) ra[i] = xs[tr * 4 + i][kk];
            rbv[0] = ws[kk][2 * tc];
            rbv[1] = ws[kk][2 * tc + 1];
            rbv[2] = ws[kk][2 * tc + 32];
            rbv[3] = ws[kk][2 * tc + 33];
#pragma unroll
            for (int i = 0; i < 4; i++)
#pragma unroll
                for (int j = 0; j < 4; j++)
                    acc[i][j] = fmaf(ra[i], rbv[j], acc[i][j]);
        }
        __syncthreads();
    }

    int cbase = cb * 64;
#pragma unroll
    for (int i = 0; i < 4; i++) {
        int gr = row0 + tr * 4 + i;
        if (gr >= ROWS) continue;
        float* dst = out + (size_t)gr * EMB + cbase;
        dst[2 * tc]      = acc[i][0] + bo[cbase + 2 * tc];
        dst[2 * tc + 1]  = acc[i][1] + bo[cbase + 2 * tc + 1];
        dst[2 * tc + 32] = acc[i][2] + bo[cbase + 2 * tc + 32];
        dst[2 * tc + 33] = acc[i][3] + bo[cbase + 2 * tc + 33];
    }
}

// ---------------- launch -----------------------------------------------------
extern "C" void kernel_launch(void* const* d_in, const int* in_sizes, int n_in,
                              void* d_out, int out_size)
{
    const float* x  = (const float*)d_in[0];
    const float* Wq = (const float*)d_in[1];
    const float* Wk = (const float*)d_in[2];
    const float* Wv = (const float*)d_in[3];
    const float* Wo = (const float*)d_in[4];
    const float* bo = (const float*)d_in[5];
    float* out = (float*)d_out;

    // phi(2) exactly as the Python host loop computes it (glibc pow, doubles)
    double xg = 2.0;
    for (int it = 0; it < 10; ++it) xg = pow(1.0 + xg, 1.0 / 3.0);
    float inv_g = (float)(1.0 / xg);

    const int ATTN_SMEM = 4 * 64 * 65 * (int)sizeof(float);   // 66560 B
    cudaFuncSetAttribute(attn_kernel,
                         cudaFuncAttributeMaxDynamicSharedMemorySize, ATTN_SMEM);

    init_freqs<<<1, 192>>>(inv_g);
    init_trig<<<(SEQL * HDS * NF + 255) / 256, 256>>>();

    dim3 qkv_grid((ROWS + 63) / 64, HDS, 3);
    qkv_kernel<<<qkv_grid, 256>>>(x, Wq, Wk, Wv);

    dim3 attn_grid((SEQL + 63) / 64, BB * HDS);
    attn_kernel<<<attn_grid, 256, ATTN_SMEM>>>();

    dim3 proj_grid((ROWS + 63) / 64, EMB / 64);
    proj_kernel<<<proj_grid, 256>>>(Wo, bo, out);
}

// round 5
// speedup vs baseline: 1.6576x; 1.6576x over previous
#include <cuda_runtime.h>
#include <math.h>
#include <stdint.h>

#define BB 16
#define SEQL 1025
#define EMB 384
#define HDS 6
#define HD 64
#define NF 32
#define ROWS (BB*SEQL)
#define BHN (BB*HDS)

__device__ float g_q[(size_t)BHN*SEQL*HD];   // [b,h,s,d]
__device__ float g_k[(size_t)BHN*SEQL*HD];
__device__ float g_v[(size_t)BHN*SEQL*HD];
__device__ float g_ao[(size_t)ROWS*EMB];
__device__ float g_cos[SEQL*HDS*NF];
__device__ float g_sin[SEQL*HDS*NF];
__device__ float g_freqs[HDS*NF*2];

// ===================== mma.sync helpers (portable PTX, compute_103-safe) ====
__device__ __forceinline__ uint32_t f2tf32(float x) {
    uint32_t r;
    asm("cvt.rna.tf32.f32 %0, %1;" : "=r"(r) : "f"(x));
    return r;
}
__device__ __forceinline__ void mma_tf32(float* d, const uint32_t* a,
                                         uint32_t b0, uint32_t b1) {
    asm volatile(
        "mma.sync.aligned.m16n8k8.row.col.f32.tf32.tf32.f32 "
        "{%0,%1,%2,%3}, {%4,%5,%6,%7}, {%8,%9}, {%0,%1,%2,%3};"
        : "+f"(d[0]), "+f"(d[1]), "+f"(d[2]), "+f"(d[3])
        : "r"(a[0]), "r"(a[1]), "r"(a[2]), "r"(a[3]), "r"(b0), "r"(b1));
}

// ===================== init (bit-matched constants) =====================
__device__ __forceinline__ float erfinv_xla(float x) {
    float w = -log1pf(-__fmul_rn(x, x));
    float p;
    if (w < 5.0f) {
        w = w - 2.5f;
        p = 2.81022636e-08f;
        p = fmaf(p, w, 3.43273939e-07f);
        p = fmaf(p, w, -3.5233877e-06f);
        p = fmaf(p, w, -4.39150654e-06f);
        p = fmaf(p, w, 0.00021858087f);
        p = fmaf(p, w, -0.00125372503f);
        p = fmaf(p, w, -0.00417768164f);
        p = fmaf(p, w, 0.246640727f);
        p = fmaf(p, w, 1.50140941f);
    } else {
        w = sqrtf(w) - 3.0f;
        p = -0.000200214257f;
        p = fmaf(p, w, 0.000100950558f);
        p = fmaf(p, w, 0.00134934322f);
        p = fmaf(p, w, -0.00367342844f);
        p = fmaf(p, w, 0.00573950773f);
        p = fmaf(p, w, -0.0076224613f);
        p = fmaf(p, w, 0.00943887047f);
        p = fmaf(p, w, 1.00167406f);
        p = fmaf(p, w, 2.83297682f);
    }
    return p * x;
}

__global__ void init_freqs(float inv_g) {
    int n = threadIdx.x;
    if (n >= HDS * NF) return;
    float alpha0 = powf(inv_g, 1.0f);
    float alpha1 = powf(inv_g, 2.0f);
    float fi = (float)(n + 1);
    float z0 = fmodf(__fmul_rn(fi, alpha0), 1.0f);
    float z1 = fmodf(__fmul_rn(fi, alpha1), 1.0f);
    float d0 = erfinv_xla(__fmul_rn(2.0f, z0) - 1.0f);
    float d1 = erfinv_xla(__fmul_rn(2.0f, z1) - 1.0f);
    float nrm = sqrtf(__fadd_rn(__fmul_rn(d0, d0), __fmul_rn(d1, d1)));
    d0 = __fdiv_rn(d0, nrm);
    d1 = __fdiv_rn(d1, nrm);
    int f = n % NF;
    float t = __fmul_rn((float)f, (1.0f / 31.0f));
    float omega = __fmul_rn(0.1f, powf(10000.0f, t));
    g_freqs[n * 2 + 0] = __fmul_rn(d0, omega);
    g_freqs[n * 2 + 1] = __fmul_rn(d1, omega);
}

__global__ void init_trig() {
    int idx = blockIdx.x * blockDim.x + threadIdx.x;
    if (idx >= SEQL * HDS * NF) return;
    int s = idx / (HDS * NF);
    int r = idx % (HDS * NF);
    float c0 = 0.f, c1 = 0.f;
    if (s > 0) {
        int p = s - 1;
        int xi = p % 32, yi = p / 32;
        c0 = __fmul_rn(__fdiv_rn((float)xi, 31.0f), 2.0f) - 1.0f;
        c1 = __fmul_rn(__fdiv_rn((float)yi, 31.0f), 2.0f) - 1.0f;
    }
    float th = __fadd_rn(__fmul_rn(g_freqs[r * 2 + 0], c0), __fmul_rn(g_freqs[r * 2 + 1], c1));
    g_cos[idx] = cosf(th);
    g_sin[idx] = sinf(th);
}

// ===================== QKV + fused RoPE =====================
__global__ void __launch_bounds__(256) qkv_kernel(
    const float* __restrict__ x, const float* __restrict__ Wq,
    const float* __restrict__ Wk, const float* __restrict__ Wv)
{
    int rb = blockIdx.x, h = blockIdx.y, z = blockIdx.z;
    const float* W = (z == 0) ? Wq : ((z == 1) ? Wk : Wv);
    float* outb = (z == 0) ? g_q : ((z == 1) ? g_k : g_v);

    __shared__ float xs[64][33];
    __shared__ float ws[32][64];

    int tid = threadIdx.x;
    int tr = tid >> 4, tc = tid & 15;
    float acc[4][4] = {};
    int row0 = rb * 64;

    for (int k0 = 0; k0 < EMB; k0 += 32) {
#pragma unroll
        for (int u = 0; u < 8; u++) {
            int e = tid + 256 * u;
            int rr = e >> 5, kk = e & 31;
            int gr = row0 + rr;
            xs[rr][kk] = (gr < ROWS) ? x[(size_t)gr * EMB + k0 + kk] : 0.f;
        }
#pragma unroll
        for (int u = 0; u < 8; u++) {
            int e = tid + 256 * u;
            int kk = e >> 6, cc = e & 63;
            ws[kk][cc] = W[(size_t)(k0 + kk) * EMB + h * 64 + cc];
        }
        __syncthreads();
#pragma unroll
        for (int kk = 0; kk < 32; kk++) {
            float ra[4], rbv[4];
#pragma unroll
            for (int i = 0; i < 4; i++) ra[i] = xs[tr * 4 + i][kk];
            rbv[0] = ws[kk][2 * tc];
            rbv[1] = ws[kk][2 * tc + 1];
            rbv[2] = ws[kk][2 * tc + 32];
            rbv[3] = ws[kk][2 * tc + 33];
#pragma unroll
            for (int i = 0; i < 4; i++)
#pragma unroll
                for (int j = 0; j < 4; j++)
                    acc[i][j] = fmaf(ra[i], rbv[j], acc[i][j]);
        }
        __syncthreads();
    }

#pragma unroll
    for (int i = 0; i < 4; i++) {
        int gr = row0 + tr * 4 + i;
        if (gr >= ROWS) continue;
        int b = gr / SEQL, s = gr % SEQL;
        float* dst = outb + ((size_t)(b * HDS + h) * SEQL + s) * HD;
        if (z < 2) {
#pragma unroll
            for (int j = 0; j < 2; j++) {
                int f = 2 * tc + j;
                float cv = g_cos[(s * HDS + h) * NF + f];
                float sv = g_sin[(s * HDS + h) * NF + f];
                float lo = acc[i][j], hi = acc[i][j + 2];
                dst[f]      = lo * cv - hi * sv;
                dst[f + 32] = lo * sv + hi * cv;
            }
        } else {
            dst[2 * tc]      = acc[i][0];
            dst[2 * tc + 1]  = acc[i][1];
            dst[2 * tc + 32] = acc[i][2];
            dst[2 * tc + 33] = acc[i][3];
        }
    }
}

// ===================== Flash attention on mma.sync tf32 =====================
// SMEM word offsets: P/Qstage stride 68, K stride 68, V stride 72
#define PS_OFF 0              // 128*68 = 8704 words (Q staging, then P)
#define KHI_OFF 8704          // 64*68 = 4352
#define KLO_OFF 13056
#define VHI_OFF 17408         // 64*72 = 4608
#define VLO_OFF 22016
#define ATTN_WORDS 26624
#define ATTN_SMEM (ATTN_WORDS*4)

__global__ void __launch_bounds__(256, 1) attn_mma_kernel() {
    extern __shared__ float sm[];
    float*    Ps  = sm + PS_OFF;
    uint32_t* Khi = (uint32_t*)(sm + KHI_OFF);
    uint32_t* Klo = (uint32_t*)(sm + KLO_OFF);
    uint32_t* Vhi = (uint32_t*)(sm + VHI_OFF);
    uint32_t* Vlo = (uint32_t*)(sm + VLO_OFF);

    int tid = threadIdx.x;
    int wid = tid >> 5, lane = tid & 31;
    int g = lane >> 2, tig = lane & 3;
    int wrow = wid * 16;
    int qb = blockIdx.x, bh = blockIdx.y;

    const float* Q = g_q + (size_t)bh * SEQL * HD;
    const float* K = g_k + (size_t)bh * SEQL * HD;
    const float* V = g_v + (size_t)bh * SEQL * HD;

    // ---- stage Q (scaled by 1/8) into Ps, then pull fragments to registers
#pragma unroll
    for (int u = 0; u < 8; u++) {
        int idx = tid + 256 * u;
        int rr = idx >> 4, c4 = idx & 15;
        int s = qb * 128 + rr;
        float4 v = make_float4(0.f, 0.f, 0.f, 0.f);
        if (s < SEQL) v = *(const float4*)(Q + (size_t)s * HD + c4 * 4);
        v.x *= 0.125f; v.y *= 0.125f; v.z *= 0.125f; v.w *= 0.125f;
        *(float4*)(Ps + rr * 68 + c4 * 4) = v;
    }
    __syncthreads();

    uint32_t qhi[8][4], qlo[8][4];
#pragma unroll
    for (int ks = 0; ks < 8; ks++) {
#pragma unroll
        for (int j = 0; j < 4; j++) {
            int rr = wrow + g + (j & 1) * 8;
            int cc = 8 * ks + tig + (j >> 1) * 4;
            float x = Ps[rr * 68 + cc];
            uint32_t h = f2tf32(x);
            qhi[ks][j] = h;
            qlo[ks][j] = f2tf32(x - __uint_as_float(h));
        }
    }
    __syncthreads();

    float o[8][4] = {};
    float m0 = -INFINITY, m1 = -INFINITY, l0 = 0.f, l1 = 0.f;

    for (int t = 0; t < 17; t++) {
        // ---- cooperative K/V load + tf32 hi/lo split
#pragma unroll
        for (int u = 0; u < 4; u++) {
            int idx = tid + 256 * u;
            int rr = idx >> 4, c4 = idx & 15;
            int s = t * 64 + rr;
            float4 kv = make_float4(0.f, 0.f, 0.f, 0.f);
            float4 vv = make_float4(0.f, 0.f, 0.f, 0.f);
            if (s < SEQL) {
                kv = *(const float4*)(K + (size_t)s * HD + c4 * 4);
                vv = *(const float4*)(V + (size_t)s * HD + c4 * 4);
            }
            uint4 kh, kl, vh, vl;
            kh.x = f2tf32(kv.x); kl.x = f2tf32(kv.x - __uint_as_float(kh.x));
            kh.y = f2tf32(kv.y); kl.y = f2tf32(kv.y - __uint_as_float(kh.y));
            kh.z = f2tf32(kv.z); kl.z = f2tf32(kv.z - __uint_as_float(kh.z));
            kh.w = f2tf32(kv.w); kl.w = f2tf32(kv.w - __uint_as_float(kh.w));
            vh.x = f2tf32(vv.x); vl.x = f2tf32(vv.x - __uint_as_float(vh.x));
            vh.y = f2tf32(vv.y); vl.y = f2tf32(vv.y - __uint_as_float(vh.y));
            vh.z = f2tf32(vv.z); vl.z = f2tf32(vv.z - __uint_as_float(vh.z));
            vh.w = f2tf32(vv.w); vl.w = f2tf32(vv.w - __uint_as_float(vh.w));
            *(uint4*)(Khi + rr * 68 + c4 * 4) = kh;
            *(uint4*)(Klo + rr * 68 + c4 * 4) = kl;
            *(uint4*)(Vhi + rr * 72 + c4 * 4) = vh;
            *(uint4*)(Vlo + rr * 72 + c4 * 4) = vl;
        }
        __syncthreads();

        // ---- S = Q K^T (3-pass hi/lo), accumulators in regs
        float s[8][4] = {};
#pragma unroll
        for (int ks = 0; ks < 8; ks++) {
#pragma unroll
            for (int nb = 0; nb < 8; nb++) {
                int row = nb * 8 + g;
                int c0 = 8 * ks + tig;
                uint32_t bh0 = Khi[row * 68 + c0];
                uint32_t bh1 = Khi[row * 68 + c0 + 4];
                uint32_t bl0 = Klo[row * 68 + c0];
                uint32_t bl1 = Klo[row * 68 + c0 + 4];
                mma_tf32(s[nb], qhi[ks], bh0, bh1);
                mma_tf32(s[nb], qhi[ks], bl0, bl1);
                mma_tf32(s[nb], qlo[ks], bh0, bh1);
            }
        }

        // ---- mask invalid kv columns (only final tile has any)
        if (t == 16) {
#pragma unroll
            for (int nb = 0; nb < 8; nb++) {
                int c = 1024 + nb * 8 + 2 * tig;
                if (c >= SEQL)     { s[nb][0] = -INFINITY; s[nb][2] = -INFINITY; }
                if (c + 1 >= SEQL) { s[nb][1] = -INFINITY; s[nb][3] = -INFINITY; }
            }
        }

        // ---- online softmax (rows g and g+8; quad-wide reductions)
        float rm0 = -INFINITY, rm1 = -INFINITY;
#pragma unroll
        for (int nb = 0; nb < 8; nb++) {
            rm0 = fmaxf(rm0, fmaxf(s[nb][0], s[nb][1]));
            rm1 = fmaxf(rm1, fmaxf(s[nb][2], s[nb][3]));
        }
        rm0 = fmaxf(rm0, __shfl_xor_sync(0xffffffffu, rm0, 1));
        rm0 = fmaxf(rm0, __shfl_xor_sync(0xffffffffu, rm0, 2));
        rm1 = fmaxf(rm1, __shfl_xor_sync(0xffffffffu, rm1, 1));
        rm1 = fmaxf(rm1, __shfl_xor_sync(0xffffffffu, rm1, 2));
        float nm0 = fmaxf(m0, rm0), nm1 = fmaxf(m1, rm1);
        float corr0 = __expf(m0 - nm0), corr1 = __expf(m1 - nm1);
        m0 = nm0; m1 = nm1;

        float rs0 = 0.f, rs1 = 0.f;
#pragma unroll
        for (int nb = 0; nb < 8; nb++) {
            s[nb][0] = __expf(s[nb][0] - m0);
            s[nb][1] = __expf(s[nb][1] - m0);
            s[nb][2] = __expf(s[nb][2] - m1);
            s[nb][3] = __expf(s[nb][3] - m1);
            rs0 += s[nb][0] + s[nb][1];
            rs1 += s[nb][2] + s[nb][3];
        }
        rs0 += __shfl_xor_sync(0xffffffffu, rs0, 1);
        rs0 += __shfl_xor_sync(0xffffffffu, rs0, 2);
        rs1 += __shfl_xor_sync(0xffffffffu, rs1, 1);
        rs1 += __shfl_xor_sync(0xffffffffu, rs1, 2);
        l0 = l0 * corr0 + rs0;
        l1 = l1 * corr1 + rs1;

#pragma unroll
        for (int nb = 0; nb < 8; nb++) {
            o[nb][0] *= corr0; o[nb][1] *= corr0;
            o[nb][2] *= corr1; o[nb][3] *= corr1;
        }

        // ---- P to SMEM (own warp's 16 rows only)
#pragma unroll
        for (int nb = 0; nb < 8; nb++) {
            *(float2*)(Ps + (wrow + g) * 68 + nb * 8 + 2 * tig)     = make_float2(s[nb][0], s[nb][1]);
            *(float2*)(Ps + (wrow + g + 8) * 68 + nb * 8 + 2 * tig) = make_float2(s[nb][2], s[nb][3]);
        }
        __syncwarp();

        // ---- O += P V (P single tf32, V hi/lo 2-pass)
#pragma unroll
        for (int ks = 0; ks < 8; ks++) {
            uint32_t pa[4];
            pa[0] = f2tf32(Ps[(wrow + g) * 68 + 8 * ks + tig]);
            pa[1] = f2tf32(Ps[(wrow + g + 8) * 68 + 8 * ks + tig]);
            pa[2] = f2tf32(Ps[(wrow + g) * 68 + 8 * ks + tig + 4]);
            pa[3] = f2tf32(Ps[(wrow + g + 8) * 68 + 8 * ks + tig + 4]);
#pragma unroll
            for (int nb = 0; nb < 8; nb++) {
                int r0 = 8 * ks + tig;
                int cc = nb * 8 + g;
                uint32_t vh0 = Vhi[r0 * 72 + cc];
                uint32_t vh1 = Vhi[(r0 + 4) * 72 + cc];
                uint32_t vl0 = Vlo[r0 * 72 + cc];
                uint32_t vl1 = Vlo[(r0 + 4) * 72 + cc];
                mma_tf32(o[nb], pa, vh0, vh1);
                mma_tf32(o[nb], pa, vl0, vl1);
            }
        }
        __syncthreads();   // K/V/P consumed; safe to overwrite next tile
    }

    // ---- normalize + store
    float inv0 = 1.0f / l0, inv1 = 1.0f / l1;
    int b = bh / HDS, h = bh % HDS;
    int s0 = qb * 128 + wrow + g;
    int s1 = s0 + 8;
#pragma unroll
    for (int nb = 0; nb < 8; nb++) {
        int cc = nb * 8 + 2 * tig;
        if (s0 < SEQL) {
            float* dst = g_ao + ((size_t)b * SEQL + s0) * EMB + h * HD + cc;
            *(float2*)dst = make_float2(o[nb][0] * inv0, o[nb][1] * inv0);
        }
        if (s1 < SEQL) {
            float* dst = g_ao + ((size_t)b * SEQL + s1) * EMB + h * HD + cc;
            *(float2*)dst = make_float2(o[nb][2] * inv1, o[nb][3] * inv1);
        }
    }
}

// ===================== Output projection =====================
__global__ void __launch_bounds__(256) proj_kernel(
    const float* __restrict__ Wo, const float* __restrict__ bo,
    float* __restrict__ out)
{
    int rb = blockIdx.x, cb = blockIdx.y;

    __shared__ float xs[64][33];
    __shared__ float ws[32][64];

    int tid = threadIdx.x;
    int tr = tid >> 4, tc = tid & 15;
    float acc[4][4] = {};
    int row0 = rb * 64;

    for (int k0 = 0; k0 < EMB; k0 += 32) {
#pragma unroll
        for (int u = 0; u < 8; u++) {
            int e = tid + 256 * u;
            int rr = e >> 5, kk = e & 31;
            int gr = row0 + rr;
            xs[rr][kk] = (gr < ROWS) ? g_ao[(size_t)gr * EMB + k0 + kk] : 0.f;
        }
#pragma unroll
        for (int u = 0; u < 8; u++) {
            int e = tid + 256 * u;
            int kk = e >> 6, cc = e & 63;
            ws[kk][cc] = Wo[(size_t)(k0 + kk) * EMB + cb * 64 + cc];
        }
        __syncthreads();
#pragma unroll
        for (int kk = 0; kk < 32; kk++) {
            float ra[4], rbv[4];
#pragma unroll
            for (int i = 0; i < 4; i++) ra[i] = xs[tr * 4 + i][kk];
            rbv[0] = ws[kk][2 * tc];
            rbv[1] = ws[kk][2 * tc + 1];
            rbv[2] = ws[kk][2 * tc + 32];
            rbv[3] = ws[kk][2 * tc + 33];
#pragma unroll
            for (int i = 0; i < 4; i++)
#pragma unroll
                for (int j = 0; j < 4; j++)
                    acc[i][j] = fmaf(ra[i], rbv[j], acc[i][j]);
        }
        __syncthreads();
    }

    int cbase = cb * 64;
#pragma unroll
    for (int i = 0; i < 4; i++) {
        int gr = row0 + tr * 4 + i;
        if (gr >= ROWS) continue;
        float* dst = out + (size_t)gr * EMB + cbase;
        dst[2 * tc]      = acc[i][0] + bo[cbase + 2 * tc];
        dst[2 * tc + 1]  = acc[i][1] + bo[cbase + 2 * tc + 1];
        dst[2 * tc + 32] = acc[i][2] + bo[cbase + 2 * tc + 32];
        dst[2 * tc + 33] = acc[i][3] + bo[cbase + 2 * tc + 33];
    }
}

// ===================== launch =====================
extern "C" void kernel_launch(void* const* d_in, const int* in_sizes, int n_in,
                              void* d_out, int out_size)
{
    const float* x  = (const float*)d_in[0];
    const float* Wq = (const float*)d_in[1];
    const float* Wk = (const float*)d_in[2];
    const float* Wv = (const float*)d_in[3];
    const float* Wo = (const float*)d_in[4];
    const float* bo = (const float*)d_in[5];
    float* out = (float*)d_out;

    double xg = 2.0;
    for (int it = 0; it < 10; ++it) xg = pow(1.0 + xg, 1.0 / 3.0);
    float inv_g = (float)(1.0 / xg);

    cudaFuncSetAttribute(attn_mma_kernel,
                         cudaFuncAttributeMaxDynamicSharedMemorySize, ATTN_SMEM);

    init_freqs<<<1, 192>>>(inv_g);
    init_trig<<<(SEQL * HDS * NF + 255) / 256, 256>>>();

    dim3 qkv_grid((ROWS + 63) / 64, HDS, 3);
    qkv_kernel<<<qkv_grid, 256>>>(x, Wq, Wk, Wv);

    dim3 attn_grid(9, BHN);
    attn_mma_kernel<<<attn_grid, 256, ATTN_SMEM>>>();

    dim3 proj_grid((ROWS + 63) / 64, EMB / 64);
    proj_kernel<<<proj_grid, 256>>>(Wo, bo, out);
}

// round 6
// speedup vs baseline: 2.0598x; 1.2426x over previous
#include <cuda_runtime.h>
#include <math.h>
#include <stdint.h>

#define BB 16
#define SEQL 1025
#define EMB 384
#define HDS 6
#define HD 64
#define NF 32
#define ROWS (BB*SEQL)
#define BHN (BB*HDS)

__device__ float g_q[(size_t)BHN*SEQL*HD];   // [b,h,s,d]
__device__ float g_k[(size_t)BHN*SEQL*HD];
__device__ float g_v[(size_t)BHN*SEQL*HD];
__device__ float g_ao[(size_t)ROWS*EMB];
__device__ float g_cos[SEQL*HDS*NF];
__device__ float g_sin[SEQL*HDS*NF];
__device__ float g_freqs[HDS*NF*2];

// ===================== mma.sync helpers =====================
__device__ __forceinline__ uint32_t f2tf32(float x) {
    uint32_t r;
    asm("cvt.rna.tf32.f32 %0, %1;" : "=r"(r) : "f"(x));
    return r;
}
__device__ __forceinline__ void mma_tf32(float* d, const uint32_t* a,
                                         uint32_t b0, uint32_t b1) {
    asm volatile(
        "mma.sync.aligned.m16n8k8.row.col.f32.tf32.tf32.f32 "
        "{%0,%1,%2,%3}, {%4,%5,%6,%7}, {%8,%9}, {%0,%1,%2,%3};"
        : "+f"(d[0]), "+f"(d[1]), "+f"(d[2]), "+f"(d[3])
        : "r"(a[0]), "r"(a[1]), "r"(a[2]), "r"(a[3]), "r"(b0), "r"(b1));
}

// ===================== init (bit-matched constants) =====================
__device__ __forceinline__ float erfinv_xla(float x) {
    float w = -log1pf(-__fmul_rn(x, x));
    float p;
    if (w < 5.0f) {
        w = w - 2.5f;
        p = 2.81022636e-08f;
        p = fmaf(p, w, 3.43273939e-07f);
        p = fmaf(p, w, -3.5233877e-06f);
        p = fmaf(p, w, -4.39150654e-06f);
        p = fmaf(p, w, 0.00021858087f);
        p = fmaf(p, w, -0.00125372503f);
        p = fmaf(p, w, -0.00417768164f);
        p = fmaf(p, w, 0.246640727f);
        p = fmaf(p, w, 1.50140941f);
    } else {
        w = sqrtf(w) - 3.0f;
        p = -0.000200214257f;
        p = fmaf(p, w, 0.000100950558f);
        p = fmaf(p, w, 0.00134934322f);
        p = fmaf(p, w, -0.00367342844f);
        p = fmaf(p, w, 0.00573950773f);
        p = fmaf(p, w, -0.0076224613f);
        p = fmaf(p, w, 0.00943887047f);
        p = fmaf(p, w, 1.00167406f);
        p = fmaf(p, w, 2.83297682f);
    }
    return p * x;
}

__global__ void init_freqs(float inv_g) {
    int n = threadIdx.x;
    if (n >= HDS * NF) return;
    float alpha0 = powf(inv_g, 1.0f);
    float alpha1 = powf(inv_g, 2.0f);
    float fi = (float)(n + 1);
    float z0 = fmodf(__fmul_rn(fi, alpha0), 1.0f);
    float z1 = fmodf(__fmul_rn(fi, alpha1), 1.0f);
    float d0 = erfinv_xla(__fmul_rn(2.0f, z0) - 1.0f);
    float d1 = erfinv_xla(__fmul_rn(2.0f, z1) - 1.0f);
    float nrm = sqrtf(__fadd_rn(__fmul_rn(d0, d0), __fmul_rn(d1, d1)));
    d0 = __fdiv_rn(d0, nrm);
    d1 = __fdiv_rn(d1, nrm);
    int f = n % NF;
    float t = __fmul_rn((float)f, (1.0f / 31.0f));
    float omega = __fmul_rn(0.1f, powf(10000.0f, t));
    g_freqs[n * 2 + 0] = __fmul_rn(d0, omega);
    g_freqs[n * 2 + 1] = __fmul_rn(d1, omega);
}

__global__ void init_trig() {
    int idx = blockIdx.x * blockDim.x + threadIdx.x;
    if (idx >= SEQL * HDS * NF) return;
    int s = idx / (HDS * NF);
    int r = idx % (HDS * NF);
    float c0 = 0.f, c1 = 0.f;
    if (s > 0) {
        int p = s - 1;
        int xi = p % 32, yi = p / 32;
        c0 = __fmul_rn(__fdiv_rn((float)xi, 31.0f), 2.0f) - 1.0f;
        c1 = __fmul_rn(__fdiv_rn((float)yi, 31.0f), 2.0f) - 1.0f;
    }
    float th = __fadd_rn(__fmul_rn(g_freqs[r * 2 + 0], c0), __fmul_rn(g_freqs[r * 2 + 1], c1));
    g_cos[idx] = cosf(th);
    g_sin[idx] = sinf(th);
}

// ===================== tensorized GEMM: QKV (+RoPE) and proj (+bias) ========
// Tile: 128 rows x 64 cols, K=384 in 6 chunks of 64.
// SMEM: xs[128][68] floats, Wp[64 n][36 uint4] packed (bh0,bh1,bl0,bl1)
#define GW_OFF 8704
#define GEMM_SMEM ((8704 + 9216) * 4)   // 71680 B

struct GemmAcc { float o[8][4]; };

__device__ __forceinline__ void gemm_core_128x64(
    const float* __restrict__ src, int src_is_x,   // x global [rows][384]
    const float* __restrict__ W, int colbase,
    int row0, float* xs, uint4* Wp, GemmAcc& A)
{
    int tid = threadIdx.x;
    int wid = tid >> 5, lane = tid & 31;
    int g = lane >> 2, tig = lane & 3;
    int wrow = wid * 16;
    (void)src_is_x;

    for (int c = 0; c < 6; c++) {
        int k0 = c * 64;
        // ---- x chunk -> xs (float, stride 68)
#pragma unroll
        for (int u = 0; u < 8; u++) {
            int idx = tid + 256 * u;
            int rr = idx >> 4, c4 = idx & 15;
            int gr = row0 + rr;
            float4 v = make_float4(0.f, 0.f, 0.f, 0.f);
            if (gr < ROWS) v = *(const float4*)(src + (size_t)gr * EMB + k0 + 4 * c4);
            *(float4*)(xs + rr * 68 + 4 * c4) = v;
        }
        // ---- W chunk -> packed hi/lo uint4 slots
#pragma unroll
        for (int u = 0; u < 2; u++) {
            int id = tid + 256 * u;
            int n = id & 63, ks = id >> 6;   // ks 0..7 over both u
            float wv[8];
#pragma unroll
            for (int j = 0; j < 8; j++)
                wv[j] = W[(size_t)(k0 + 8 * ks + j) * EMB + colbase + n];
            uint32_t hi[8], lo[8];
#pragma unroll
            for (int j = 0; j < 8; j++) {
                hi[j] = f2tf32(wv[j]);
                lo[j] = f2tf32(wv[j] - __uint_as_float(hi[j]));
            }
            uint4* dst = Wp + n * 36 + ks * 4;
            dst[0] = make_uint4(hi[0], hi[4], lo[0], lo[4]);
            dst[1] = make_uint4(hi[1], hi[5], lo[1], lo[5]);
            dst[2] = make_uint4(hi[2], hi[6], lo[2], lo[6]);
            dst[3] = make_uint4(hi[3], hi[7], lo[3], lo[7]);
        }
        __syncthreads();

#pragma unroll
        for (int ks = 0; ks < 8; ks++) {
            float a0 = xs[(wrow + g) * 68 + 8 * ks + tig];
            float a1 = xs[(wrow + g + 8) * 68 + 8 * ks + tig];
            float a2 = xs[(wrow + g) * 68 + 8 * ks + tig + 4];
            float a3 = xs[(wrow + g + 8) * 68 + 8 * ks + tig + 4];
            uint32_t ahi[4], alo[4];
            ahi[0] = f2tf32(a0); alo[0] = f2tf32(a0 - __uint_as_float(ahi[0]));
            ahi[1] = f2tf32(a1); alo[1] = f2tf32(a1 - __uint_as_float(ahi[1]));
            ahi[2] = f2tf32(a2); alo[2] = f2tf32(a2 - __uint_as_float(ahi[2]));
            ahi[3] = f2tf32(a3); alo[3] = f2tf32(a3 - __uint_as_float(ahi[3]));
#pragma unroll
            for (int nb = 0; nb < 8; nb++) {
                uint4 w4 = Wp[(nb * 8 + g) * 36 + ks * 4 + tig];
                mma_tf32(A.o[nb], ahi, w4.x, w4.y);
                mma_tf32(A.o[nb], ahi, w4.z, w4.w);
                mma_tf32(A.o[nb], alo, w4.x, w4.y);
            }
        }
        __syncthreads();
    }
}

__global__ void __launch_bounds__(256) qkv_mma_kernel(
    const float* __restrict__ x, const float* __restrict__ Wq,
    const float* __restrict__ Wk, const float* __restrict__ Wv)
{
    extern __shared__ float sm[];
    float* xs = sm;
    uint4* Wp = (uint4*)(sm + GW_OFF);

    int tid = threadIdx.x;
    int wid = tid >> 5, lane = tid & 31;
    int g = lane >> 2, tig = lane & 3;
    int wrow = wid * 16;
    int rb = blockIdx.x, h = blockIdx.y, z = blockIdx.z;
    const float* W = (z == 0) ? Wq : ((z == 1) ? Wk : Wv);
    int row0 = rb * 128;

    GemmAcc A;
#pragma unroll
    for (int nb = 0; nb < 8; nb++)
#pragma unroll
        for (int j = 0; j < 4; j++) A.o[nb][j] = 0.f;

    gemm_core_128x64(x, 1, W, h * 64, row0, xs, Wp, A);

    if (z < 2) {
        float* base = (z == 0) ? g_q : g_k;
#pragma unroll
        for (int nb = 0; nb < 4; nb++)
#pragma unroll
            for (int jj = 0; jj < 4; jj++) {
                int gr = row0 + wrow + g + 8 * (jj >> 1);
                if (gr >= ROWS) continue;
                int b = gr / SEQL, s = gr % SEQL;
                int f = 8 * nb + 2 * tig + (jj & 1);
                float cv = g_cos[(s * HDS + h) * NF + f];
                float sv = g_sin[(s * HDS + h) * NF + f];
                float lov = A.o[nb][jj], hiv = A.o[nb + 4][jj];
                float* dst = base + ((size_t)(b * HDS + h) * SEQL + s) * HD;
                dst[f]      = lov * cv - hiv * sv;
                dst[f + 32] = lov * sv + hiv * cv;
            }
    } else {
#pragma unroll
        for (int nb = 0; nb < 8; nb++)
#pragma unroll
            for (int jj = 0; jj < 4; jj++) {
                int gr = row0 + wrow + g + 8 * (jj >> 1);
                if (gr >= ROWS) continue;
                int b = gr / SEQL, s = gr % SEQL;
                int col = 8 * nb + 2 * tig + (jj & 1);
                g_v[((size_t)(b * HDS + h) * SEQL + s) * HD + col] = A.o[nb][jj];
            }
    }
}

__global__ void __launch_bounds__(256) proj_mma_kernel(
    const float* __restrict__ Wo, const float* __restrict__ bo,
    float* __restrict__ out)
{
    extern __shared__ float sm[];
    float* xs = sm;
    uint4* Wp = (uint4*)(sm + GW_OFF);

    int tid = threadIdx.x;
    int wid = tid >> 5, lane = tid & 31;
    int g = lane >> 2, tig = lane & 3;
    int wrow = wid * 16;
    int rb = blockIdx.x, cb = blockIdx.y;
    int row0 = rb * 128, colbase = cb * 64;

    GemmAcc A;
#pragma unroll
    for (int nb = 0; nb < 8; nb++)
#pragma unroll
        for (int j = 0; j < 4; j++) A.o[nb][j] = 0.f;

    gemm_core_128x64(g_ao, 0, Wo, colbase, row0, xs, Wp, A);

#pragma unroll
    for (int nb = 0; nb < 8; nb++)
#pragma unroll
        for (int jj = 0; jj < 4; jj++) {
            int gr = row0 + wrow + g + 8 * (jj >> 1);
            if (gr >= ROWS) continue;
            int col = 8 * nb + 2 * tig + (jj & 1);
            out[(size_t)gr * EMB + colbase + col] = A.o[nb][jj] + bo[colbase + col];
        }
}

// ===================== Flash attention (packed-K mma.sync tf32) =============
// word offsets: Ps [128][68]=8704 | Kp 2304 uint4 = 9216 words | Vs [64][72]=4608
#define PS_OFF 0
#define KP_OFF 8704
#define VS_OFF 17920
#define ATTN_SMEM (22528 * 4)   // 90112 B

__global__ void __launch_bounds__(256, 1) attn_mma_kernel() {
    extern __shared__ float sm[];
    float*    Ps = sm + PS_OFF;
    uint4*    Kp = (uint4*)(sm + KP_OFF);
    uint32_t* Vs = (uint32_t*)(sm + VS_OFF);

    int tid = threadIdx.x;
    int wid = tid >> 5, lane = tid & 31;
    int g = lane >> 2, tig = lane & 3;
    int wrow = wid * 16;
    int qb = blockIdx.x, bh = blockIdx.y;

    const float* Q = g_q + (size_t)bh * SEQL * HD;
    const float* K = g_k + (size_t)bh * SEQL * HD;
    const float* V = g_v + (size_t)bh * SEQL * HD;

    // ---- stage Q (scaled 1/8), pull A-fragments (hi/lo) into registers
#pragma unroll
    for (int u = 0; u < 8; u++) {
        int idx = tid + 256 * u;
        int rr = idx >> 4, c4 = idx & 15;
        int s = qb * 128 + rr;
        float4 v = make_float4(0.f, 0.f, 0.f, 0.f);
        if (s < SEQL) v = *(const float4*)(Q + (size_t)s * HD + c4 * 4);
        v.x *= 0.125f; v.y *= 0.125f; v.z *= 0.125f; v.w *= 0.125f;
        *(float4*)(Ps + rr * 68 + c4 * 4) = v;
    }
    __syncthreads();

    uint32_t qhi[8][4], qlo[8][4];
#pragma unroll
    for (int ks = 0; ks < 8; ks++) {
#pragma unroll
        for (int j = 0; j < 4; j++) {
            int rr = wrow + g + (j & 1) * 8;
            int cc = 8 * ks + tig + (j >> 1) * 4;
            float x = Ps[rr * 68 + cc];
            uint32_t h = f2tf32(x);
            qhi[ks][j] = h;
            qlo[ks][j] = f2tf32(x - __uint_as_float(h));
        }
    }
    __syncthreads();

    float o[8][4] = {};
    float m0 = -INFINITY, m1 = -INFINITY, l0 = 0.f, l1 = 0.f;

    for (int t = 0; t < 17; t++) {
        // ---- K pack: slot (n, ks, tig) = (Khi[n][8ks+tig], Khi[n][8ks+tig+4], Klo.., Klo..)
#pragma unroll
        for (int u = 0; u < 2; u++) {
            int id = tid + 256 * u;
            int n = id >> 3, ks = id & 7;
            int s = t * 64 + n;
            float4 ka = make_float4(0.f, 0.f, 0.f, 0.f);
            float4 kb = make_float4(0.f, 0.f, 0.f, 0.f);
            if (s < SEQL) {
                ka = *(const float4*)(K + (size_t)s * HD + 8 * ks);
                kb = *(const float4*)(K + (size_t)s * HD + 8 * ks + 4);
            }
            float kw[8] = {ka.x, ka.y, ka.z, ka.w, kb.x, kb.y, kb.z, kb.w};
            uint32_t hi[8], lo[8];
#pragma unroll
            for (int j = 0; j < 8; j++) {
                hi[j] = f2tf32(kw[j]);
                lo[j] = f2tf32(kw[j] - __uint_as_float(hi[j]));
            }
            uint4* dst = Kp + n * 36 + ks * 4;
            dst[0] = make_uint4(hi[0], hi[4], lo[0], lo[4]);
            dst[1] = make_uint4(hi[1], hi[5], lo[1], lo[5]);
            dst[2] = make_uint4(hi[2], hi[6], lo[2], lo[6]);
            dst[3] = make_uint4(hi[3], hi[7], lo[3], lo[7]);
        }
        // ---- V stage, pre-converted tf32 (single pass)
#pragma unroll
        for (int u = 0; u < 4; u++) {
            int idx = tid + 256 * u;
            int rr = idx >> 4, c4 = idx & 15;
            int s = t * 64 + rr;
            float4 v = make_float4(0.f, 0.f, 0.f, 0.f);
            if (s < SEQL) v = *(const float4*)(V + (size_t)s * HD + 4 * c4);
            uint4 vh = make_uint4(f2tf32(v.x), f2tf32(v.y), f2tf32(v.z), f2tf32(v.w));
            *(uint4*)(Vs + rr * 72 + c4 * 4) = vh;
        }
        __syncthreads();

        // ---- S = Q K^T (3-pass hi/lo), packed B-frags: 1 LDS.128 per 3 mma
        float s_[8][4] = {};
#pragma unroll
        for (int ks = 0; ks < 8; ks++) {
#pragma unroll
            for (int nb = 0; nb < 8; nb++) {
                uint4 kk = Kp[(nb * 8 + g) * 36 + ks * 4 + tig];
                mma_tf32(s_[nb], qhi[ks], kk.x, kk.y);
                mma_tf32(s_[nb], qhi[ks], kk.z, kk.w);
                mma_tf32(s_[nb], qlo[ks], kk.x, kk.y);
            }
        }

        if (t == 16) {
#pragma unroll
            for (int nb = 0; nb < 8; nb++) {
                int c = 1024 + nb * 8 + 2 * tig;
                if (c >= SEQL)     { s_[nb][0] = -INFINITY; s_[nb][2] = -INFINITY; }
                if (c + 1 >= SEQL) { s_[nb][1] = -INFINITY; s_[nb][3] = -INFINITY; }
            }
        }

        // ---- online softmax
        float rm0 = -INFINITY, rm1 = -INFINITY;
#pragma unroll
        for (int nb = 0; nb < 8; nb++) {
            rm0 = fmaxf(rm0, fmaxf(s_[nb][0], s_[nb][1]));
            rm1 = fmaxf(rm1, fmaxf(s_[nb][2], s_[nb][3]));
        }
        rm0 = fmaxf(rm0, __shfl_xor_sync(0xffffffffu, rm0, 1));
        rm0 = fmaxf(rm0, __shfl_xor_sync(0xffffffffu, rm0, 2));
        rm1 = fmaxf(rm1, __shfl_xor_sync(0xffffffffu, rm1, 1));
        rm1 = fmaxf(rm1, __shfl_xor_sync(0xffffffffu, rm1, 2));
        float nm0 = fmaxf(m0, rm0), nm1 = fmaxf(m1, rm1);
        float corr0 = __expf(m0 - nm0), corr1 = __expf(m1 - nm1);
        m0 = nm0; m1 = nm1;

        float rs0 = 0.f, rs1 = 0.f;
#pragma unroll
        for (int nb = 0; nb < 8; nb++) {
            s_[nb][0] = __expf(s_[nb][0] - m0);
            s_[nb][1] = __expf(s_[nb][1] - m0);
            s_[nb][2] = __expf(s_[nb][2] - m1);
            s_[nb][3] = __expf(s_[nb][3] - m1);
            rs0 += s_[nb][0] + s_[nb][1];
            rs1 += s_[nb][2] + s_[nb][3];
        }
        rs0 += __shfl_xor_sync(0xffffffffu, rs0, 1);
        rs0 += __shfl_xor_sync(0xffffffffu, rs0, 2);
        rs1 += __shfl_xor_sync(0xffffffffu, rs1, 1);
        rs1 += __shfl_xor_sync(0xffffffffu, rs1, 2);
        l0 = l0 * corr0 + rs0;
        l1 = l1 * corr1 + rs1;

#pragma unroll
        for (int nb = 0; nb < 8; nb++) {
            o[nb][0] *= corr0; o[nb][1] *= corr0;
            o[nb][2] *= corr1; o[nb][3] *= corr1;
        }

        // ---- P to SMEM (own warp's rows only)
#pragma unroll
        for (int nb = 0; nb < 8; nb++) {
            *(float2*)(Ps + (wrow + g) * 68 + nb * 8 + 2 * tig)     = make_float2(s_[nb][0], s_[nb][1]);
            *(float2*)(Ps + (wrow + g + 8) * 68 + nb * 8 + 2 * tig) = make_float2(s_[nb][2], s_[nb][3]);
        }
        __syncwarp();

        // ---- O += P V (P single tf32, V pre-truncated single pass)
#pragma unroll
        for (int ks = 0; ks < 8; ks++) {
            uint32_t pa[4];
            pa[0] = f2tf32(Ps[(wrow + g) * 68 + 8 * ks + tig]);
            pa[1] = f2tf32(Ps[(wrow + g + 8) * 68 + 8 * ks + tig]);
            pa[2] = f2tf32(Ps[(wrow + g) * 68 + 8 * ks + tig + 4]);
            pa[3] = f2tf32(Ps[(wrow + g + 8) * 68 + 8 * ks + tig + 4]);
#pragma unroll
            for (int nb = 0; nb < 8; nb++) {
                int r0 = 8 * ks + tig;
                int cc = nb * 8 + g;
                mma_tf32(o[nb], pa, Vs[r0 * 72 + cc], Vs[(r0 + 4) * 72 + cc]);
            }
        }
        __syncthreads();
    }

    // ---- normalize + store
    float inv0 = 1.0f / l0, inv1 = 1.0f / l1;
    int b = bh / HDS, h = bh % HDS;
    int s0 = qb * 128 + wrow + g;
    int s1 = s0 + 8;
#pragma unroll
    for (int nb = 0; nb < 8; nb++) {
        int cc = nb * 8 + 2 * tig;
        if (s0 < SEQL) {
            float* dst = g_ao + ((size_t)b * SEQL + s0) * EMB + h * HD + cc;
            *(float2*)dst = make_float2(o[nb][0] * inv0, o[nb][1] * inv0);
        }
        if (s1 < SEQL) {
            float* dst = g_ao + ((size_t)b * SEQL + s1) * EMB + h * HD + cc;
            *(float2*)dst = make_float2(o[nb][2] * inv1, o[nb][3] * inv1);
        }
    }
}

// ===================== launch =====================
extern "C" void kernel_launch(void* const* d_in, const int* in_sizes, int n_in,
                              void* d_out, int out_size)
{
    const float* x  = (const float*)d_in[0];
    const float* Wq = (const float*)d_in[1];
    const float* Wk = (const float*)d_in[2];
    const float* Wv = (const float*)d_in[3];
    const float* Wo = (const float*)d_in[4];
    const float* bo = (const float*)d_in[5];
    float* out = (float*)d_out;

    double xg = 2.0;
    for (int it = 0; it < 10; ++it) xg = pow(1.0 + xg, 1.0 / 3.0);
    float inv_g = (float)(1.0 / xg);

    cudaFuncSetAttribute(attn_mma_kernel,
                         cudaFuncAttributeMaxDynamicSharedMemorySize, ATTN_SMEM);
    cudaFuncSetAttribute(qkv_mma_kernel,
                         cudaFuncAttributeMaxDynamicSharedMemorySize, GEMM_SMEM);
    cudaFuncSetAttribute(proj_mma_kernel,
                         cudaFuncAttributeMaxDynamicSharedMemorySize, GEMM_SMEM);

    init_freqs<<<1, 192>>>(inv_g);
    init_trig<<<(SEQL * HDS * NF + 255) / 256, 256>>>();

    dim3 qkv_grid((ROWS + 127) / 128, HDS, 3);
    qkv_mma_kernel<<<qkv_grid, 256, GEMM_SMEM>>>(x, Wq, Wk, Wv);

    dim3 attn_grid(9, BHN);
    attn_mma_kernel<<<attn_grid, 256, ATTN_SMEM>>>();

    dim3 proj_grid((ROWS + 127) / 128, EMB / 64);
    proj_mma_kernel<<<proj_grid, 256, GEMM_SMEM>>>(Wo, bo, out);
}

// round 7
// speedup vs baseline: 2.1537x; 1.0456x over previous
#include <cuda_runtime.h>
#include <math.h>
#include <stdint.h>

#define BB 16
#define SEQL 1025
#define EMB 384
#define HDS 6
#define HD 64
#define NF 32
#define ROWS (BB*SEQL)
#define BHN (BB*HDS)

__device__ float g_q[(size_t)BHN*SEQL*HD];   // [b,h,s,d]
__device__ float g_k[(size_t)BHN*SEQL*HD];
__device__ float g_v[(size_t)BHN*SEQL*HD];
__device__ float g_ao[(size_t)ROWS*EMB];
__device__ float g_cos[SEQL*HDS*NF];
__device__ float g_sin[SEQL*HDS*NF];
__device__ float g_freqs[HDS*NF*2];

// ===================== mma.sync helpers =====================
__device__ __forceinline__ uint32_t f2tf32(float x) {
    uint32_t r;
    asm("cvt.rna.tf32.f32 %0, %1;" : "=r"(r) : "f"(x));
    return r;
}
__device__ __forceinline__ void mma_tf32(float* d, const uint32_t* a,
                                         uint32_t b0, uint32_t b1) {
    asm volatile(
        "mma.sync.aligned.m16n8k8.row.col.f32.tf32.tf32.f32 "
        "{%0,%1,%2,%3}, {%4,%5,%6,%7}, {%8,%9}, {%0,%1,%2,%3};"
        : "+f"(d[0]), "+f"(d[1]), "+f"(d[2]), "+f"(d[3])
        : "r"(a[0]), "r"(a[1]), "r"(a[2]), "r"(a[3]), "r"(b0), "r"(b1));
}

// ===================== init (bit-matched constants) =====================
__device__ __forceinline__ float erfinv_xla(float x) {
    float w = -log1pf(-__fmul_rn(x, x));
    float p;
    if (w < 5.0f) {
        w = w - 2.5f;
        p = 2.81022636e-08f;
        p = fmaf(p, w, 3.43273939e-07f);
        p = fmaf(p, w, -3.5233877e-06f);
        p = fmaf(p, w, -4.39150654e-06f);
        p = fmaf(p, w, 0.00021858087f);
        p = fmaf(p, w, -0.00125372503f);
        p = fmaf(p, w, -0.00417768164f);
        p = fmaf(p, w, 0.246640727f);
        p = fmaf(p, w, 1.50140941f);
    } else {
        w = sqrtf(w) - 3.0f;
        p = -0.000200214257f;
        p = fmaf(p, w, 0.000100950558f);
        p = fmaf(p, w, 0.00134934322f);
        p = fmaf(p, w, -0.00367342844f);
        p = fmaf(p, w, 0.00573950773f);
        p = fmaf(p, w, -0.0076224613f);
        p = fmaf(p, w, 0.00943887047f);
        p = fmaf(p, w, 1.00167406f);
        p = fmaf(p, w, 2.83297682f);
    }
    return p * x;
}

__global__ void init_freqs(float inv_g) {
    int n = threadIdx.x;
    if (n >= HDS * NF) return;
    float alpha0 = powf(inv_g, 1.0f);
    float alpha1 = powf(inv_g, 2.0f);
    float fi = (float)(n + 1);
    float z0 = fmodf(__fmul_rn(fi, alpha0), 1.0f);
    float z1 = fmodf(__fmul_rn(fi, alpha1), 1.0f);
    float d0 = erfinv_xla(__fmul_rn(2.0f, z0) - 1.0f);
    float d1 = erfinv_xla(__fmul_rn(2.0f, z1) - 1.0f);
    float nrm = sqrtf(__fadd_rn(__fmul_rn(d0, d0), __fmul_rn(d1, d1)));
    d0 = __fdiv_rn(d0, nrm);
    d1 = __fdiv_rn(d1, nrm);
    int f = n % NF;
    float t = __fmul_rn((float)f, (1.0f / 31.0f));
    float omega = __fmul_rn(0.1f, powf(10000.0f, t));
    g_freqs[n * 2 + 0] = __fmul_rn(d0, omega);
    g_freqs[n * 2 + 1] = __fmul_rn(d1, omega);
}

__global__ void init_trig() {
    int idx = blockIdx.x * blockDim.x + threadIdx.x;
    if (idx >= SEQL * HDS * NF) return;
    int s = idx / (HDS * NF);
    int r = idx % (HDS * NF);
    float c0 = 0.f, c1 = 0.f;
    if (s > 0) {
        int p = s - 1;
        int xi = p % 32, yi = p / 32;
        c0 = __fmul_rn(__fdiv_rn((float)xi, 31.0f), 2.0f) - 1.0f;
        c1 = __fmul_rn(__fdiv_rn((float)yi, 31.0f), 2.0f) - 1.0f;
    }
    float th = __fadd_rn(__fmul_rn(g_freqs[r * 2 + 0], c0), __fmul_rn(g_freqs[r * 2 + 1], c1));
    g_cos[idx] = cosf(th);
    g_sin[idx] = sinf(th);
}

// ===================== tensorized GEMM: QKV (+RoPE) and proj (+bias) ========
#define GW_OFF 8704
#define GEMM_SMEM ((8704 + 9216) * 4)   // 71680 B

struct GemmAcc { float o[8][4]; };

__device__ __forceinline__ void gemm_core_128x64(
    const float* __restrict__ src,
    const float* __restrict__ W, int colbase,
    int row0, float* xs, uint4* Wp, GemmAcc& A)
{
    int tid = threadIdx.x;
    int wid = tid >> 5, lane = tid & 31;
    int g = lane >> 2, tig = lane & 3;
    int wrow = wid * 16;

    for (int c = 0; c < 6; c++) {
        int k0 = c * 64;
#pragma unroll
        for (int u = 0; u < 8; u++) {
            int idx = tid + 256 * u;
            int rr = idx >> 4, c4 = idx & 15;
            int gr = row0 + rr;
            float4 v = make_float4(0.f, 0.f, 0.f, 0.f);
            if (gr < ROWS) v = *(const float4*)(src + (size_t)gr * EMB + k0 + 4 * c4);
            *(float4*)(xs + rr * 68 + 4 * c4) = v;
        }
#pragma unroll
        for (int u = 0; u < 2; u++) {
            int id = tid + 256 * u;
            int n = id & 63, ks = id >> 6;
            float wv[8];
#pragma unroll
            for (int j = 0; j < 8; j++)
                wv[j] = W[(size_t)(k0 + 8 * ks + j) * EMB + colbase + n];
            uint32_t hi[8], lo[8];
#pragma unroll
            for (int j = 0; j < 8; j++) {
                hi[j] = f2tf32(wv[j]);
                lo[j] = f2tf32(wv[j] - __uint_as_float(hi[j]));
            }
            uint4* dst = Wp + n * 36 + ks * 4;
            dst[0] = make_uint4(hi[0], hi[4], lo[0], lo[4]);
            dst[1] = make_uint4(hi[1], hi[5], lo[1], lo[5]);
            dst[2] = make_uint4(hi[2], hi[6], lo[2], lo[6]);
            dst[3] = make_uint4(hi[3], hi[7], lo[3], lo[7]);
        }
        __syncthreads();

#pragma unroll
        for (int ks = 0; ks < 8; ks++) {
            float a0 = xs[(wrow + g) * 68 + 8 * ks + tig];
            float a1 = xs[(wrow + g + 8) * 68 + 8 * ks + tig];
            float a2 = xs[(wrow + g) * 68 + 8 * ks + tig + 4];
            float a3 = xs[(wrow + g + 8) * 68 + 8 * ks + tig + 4];
            uint32_t ahi[4], alo[4];
            ahi[0] = f2tf32(a0); alo[0] = f2tf32(a0 - __uint_as_float(ahi[0]));
            ahi[1] = f2tf32(a1); alo[1] = f2tf32(a1 - __uint_as_float(ahi[1]));
            ahi[2] = f2tf32(a2); alo[2] = f2tf32(a2 - __uint_as_float(ahi[2]));
            ahi[3] = f2tf32(a3); alo[3] = f2tf32(a3 - __uint_as_float(ahi[3]));
#pragma unroll
            for (int nb = 0; nb < 8; nb++) {
                uint4 w4 = Wp[(nb * 8 + g) * 36 + ks * 4 + tig];
                mma_tf32(A.o[nb], ahi, w4.x, w4.y);
                mma_tf32(A.o[nb], ahi, w4.z, w4.w);
                mma_tf32(A.o[nb], alo, w4.x, w4.y);
            }
        }
        __syncthreads();
    }
}

__global__ void __launch_bounds__(256) qkv_mma_kernel(
    const float* __restrict__ x, const float* __restrict__ Wq,
    const float* __restrict__ Wk, const float* __restrict__ Wv)
{
    extern __shared__ float sm[];
    float* xs = sm;
    uint4* Wp = (uint4*)(sm + GW_OFF);

    int tid = threadIdx.x;
    int wid = tid >> 5, lane = tid & 31;
    int g = lane >> 2, tig = lane & 3;
    int wrow = wid * 16;
    int rb = blockIdx.x, h = blockIdx.y, z = blockIdx.z;
    const float* W = (z == 0) ? Wq : ((z == 1) ? Wk : Wv);
    int row0 = rb * 128;

    GemmAcc A;
#pragma unroll
    for (int nb = 0; nb < 8; nb++)
#pragma unroll
        for (int j = 0; j < 4; j++) A.o[nb][j] = 0.f;

    gemm_core_128x64(x, W, h * 64, row0, xs, Wp, A);

    if (z < 2) {
        float* base = (z == 0) ? g_q : g_k;
#pragma unroll
        for (int nb = 0; nb < 4; nb++)
#pragma unroll
            for (int jj = 0; jj < 4; jj++) {
                int gr = row0 + wrow + g + 8 * (jj >> 1);
                if (gr >= ROWS) continue;
                int b = gr / SEQL, s = gr % SEQL;
                int f = 8 * nb + 2 * tig + (jj & 1);
                float cv = g_cos[(s * HDS + h) * NF + f];
                float sv = g_sin[(s * HDS + h) * NF + f];
                float lov = A.o[nb][jj], hiv = A.o[nb + 4][jj];
                float* dst = base + ((size_t)(b * HDS + h) * SEQL + s) * HD;
                dst[f]      = lov * cv - hiv * sv;
                dst[f + 32] = lov * sv + hiv * cv;
            }
    } else {
#pragma unroll
        for (int nb = 0; nb < 8; nb++)
#pragma unroll
            for (int jj = 0; jj < 4; jj++) {
                int gr = row0 + wrow + g + 8 * (jj >> 1);
                if (gr >= ROWS) continue;
                int b = gr / SEQL, s = gr % SEQL;
                int col = 8 * nb + 2 * tig + (jj & 1);
                g_v[((size_t)(b * HDS + h) * SEQL + s) * HD + col] = A.o[nb][jj];
            }
    }
}

__global__ void __launch_bounds__(256) proj_mma_kernel(
    const float* __restrict__ Wo, const float* __restrict__ bo,
    float* __restrict__ out)
{
    extern __shared__ float sm[];
    float* xs = sm;
    uint4* Wp = (uint4*)(sm + GW_OFF);

    int tid = threadIdx.x;
    int wid = tid >> 5, lane = tid & 31;
    int g = lane >> 2, tig = lane & 3;
    int wrow = wid * 16;
    int rb = blockIdx.x, cb = blockIdx.y;
    int row0 = rb * 128, colbase = cb * 64;

    GemmAcc A;
#pragma unroll
    for (int nb = 0; nb < 8; nb++)
#pragma unroll
        for (int j = 0; j < 4; j++) A.o[nb][j] = 0.f;

    gemm_core_128x64(g_ao, Wo, colbase, row0, xs, Wp, A);

#pragma unroll
    for (int nb = 0; nb < 8; nb++)
#pragma unroll
        for (int jj = 0; jj < 4; jj++) {
            int gr = row0 + wrow + g + 8 * (jj >> 1);
            if (gr >= ROWS) continue;
            int col = 8 * nb + 2 * tig + (jj & 1);
            out[(size_t)gr * EMB + colbase + col] = A.o[nb][jj] + bo[colbase + col];
        }
}

// ===================== Flash attention (1-pass S, packed-K uint2) ===========
// word offsets: Ps [128][68]=8704 | Kp 64*36 uint2 = 4608 words | Vs [64][72]=4608
#define PS_OFF 0
#define KP_OFF 8704
#define VS_OFF 13312
#define ATTN_SMEM (17920 * 4)   // 71680 B

__global__ void __launch_bounds__(256, 1) attn_mma_kernel() {
    extern __shared__ float sm[];
    float*    Ps = sm + PS_OFF;
    uint2*    Kp = (uint2*)(sm + KP_OFF);
    uint32_t* Vs = (uint32_t*)(sm + VS_OFF);

    int tid = threadIdx.x;
    int wid = tid >> 5, lane = tid & 31;
    int g = lane >> 2, tig = lane & 3;
    int wrow = wid * 16;
    int qb = blockIdx.x, bh = blockIdx.y;

    const float* Q = g_q + (size_t)bh * SEQL * HD;
    const float* K = g_k + (size_t)bh * SEQL * HD;
    const float* V = g_v + (size_t)bh * SEQL * HD;

    // ---- stage Q (scaled 1/8), pull hi A-fragments into registers
#pragma unroll
    for (int u = 0; u < 8; u++) {
        int idx = tid + 256 * u;
        int rr = idx >> 4, c4 = idx & 15;
        int s = qb * 128 + rr;
        float4 v = make_float4(0.f, 0.f, 0.f, 0.f);
        if (s < SEQL) v = *(const float4*)(Q + (size_t)s * HD + c4 * 4);
        v.x *= 0.125f; v.y *= 0.125f; v.z *= 0.125f; v.w *= 0.125f;
        *(float4*)(Ps + rr * 68 + c4 * 4) = v;
    }
    __syncthreads();

    uint32_t qhi[8][4];
#pragma unroll
    for (int ks = 0; ks < 8; ks++) {
#pragma unroll
        for (int j = 0; j < 4; j++) {
            int rr = wrow + g + (j & 1) * 8;
            int cc = 8 * ks + tig + (j >> 1) * 4;
            qhi[ks][j] = f2tf32(Ps[rr * 68 + cc]);
        }
    }
    __syncthreads();

    float o[8][4] = {};
    float m0 = -INFINITY, m1 = -INFINITY, l0 = 0.f, l1 = 0.f;

    for (int t = 0; t < 17; t++) {
        // ---- K pack: slot (n, ks, tig) = uint2(Khi[n][8ks+tig], Khi[n][8ks+tig+4])
        //      store order rotated for bank-conflict-free STS.64
#pragma unroll
        for (int u = 0; u < 2; u++) {
            int id = tid + 256 * u;
            int n = id >> 3, ks = id & 7;
            int s = t * 64 + n;
            float4 ka = make_float4(0.f, 0.f, 0.f, 0.f);
            float4 kb = make_float4(0.f, 0.f, 0.f, 0.f);
            if (s < SEQL) {
                ka = *(const float4*)(K + (size_t)s * HD + 8 * ks);
                kb = *(const float4*)(K + (size_t)s * HD + 8 * ks + 4);
            }
            uint32_t hi[8];
            hi[0] = f2tf32(ka.x); hi[1] = f2tf32(ka.y);
            hi[2] = f2tf32(ka.z); hi[3] = f2tf32(ka.w);
            hi[4] = f2tf32(kb.x); hi[5] = f2tf32(kb.y);
            hi[6] = f2tf32(kb.z); hi[7] = f2tf32(kb.w);
            int rot = ((ks >> 2) + 2 * (n & 1)) & 3;
            uint2* dst = Kp + n * 36 + ks * 4;
#pragma unroll
            for (int tt = 0; tt < 4; tt++) {
                int tg = (tt + rot) & 3;
                dst[tg] = make_uint2(hi[tg], hi[tg + 4]);
            }
        }
        // ---- V stage, pre-converted tf32
#pragma unroll
        for (int u = 0; u < 4; u++) {
            int idx = tid + 256 * u;
            int rr = idx >> 4, c4 = idx & 15;
            int s = t * 64 + rr;
            float4 v = make_float4(0.f, 0.f, 0.f, 0.f);
            if (s < SEQL) v = *(const float4*)(V + (size_t)s * HD + 4 * c4);
            uint4 vh = make_uint4(f2tf32(v.x), f2tf32(v.y), f2tf32(v.z), f2tf32(v.w));
            *(uint4*)(Vs + rr * 72 + c4 * 4) = vh;
        }
        __syncthreads();

        // ---- S = Q K^T, single tf32 pass: 1 LDS.64 per mma
        float s_[8][4] = {};
#pragma unroll
        for (int ks = 0; ks < 8; ks++) {
#pragma unroll
            for (int nb = 0; nb < 8; nb++) {
                uint2 kk = Kp[(nb * 8 + g) * 36 + ks * 4 + tig];
                mma_tf32(s_[nb], qhi[ks], kk.x, kk.y);
            }
        }

        if (t == 16) {
#pragma unroll
            for (int nb = 0; nb < 8; nb++) {
                int c = 1024 + nb * 8 + 2 * tig;
                if (c >= SEQL)     { s_[nb][0] = -INFINITY; s_[nb][2] = -INFINITY; }
                if (c + 1 >= SEQL) { s_[nb][1] = -INFINITY; s_[nb][3] = -INFINITY; }
            }
        }

        // ---- online softmax
        float rm0 = -INFINITY, rm1 = -INFINITY;
#pragma unroll
        for (int nb = 0; nb < 8; nb++) {
            rm0 = fmaxf(rm0, fmaxf(s_[nb][0], s_[nb][1]));
            rm1 = fmaxf(rm1, fmaxf(s_[nb][2], s_[nb][3]));
        }
        rm0 = fmaxf(rm0, __shfl_xor_sync(0xffffffffu, rm0, 1));
        rm0 = fmaxf(rm0, __shfl_xor_sync(0xffffffffu, rm0, 2));
        rm1 = fmaxf(rm1, __shfl_xor_sync(0xffffffffu, rm1, 1));
        rm1 = fmaxf(rm1, __shfl_xor_sync(0xffffffffu, rm1, 2));
        float nm0 = fmaxf(m0, rm0), nm1 = fmaxf(m1, rm1);
        float corr0 = __expf(m0 - nm0), corr1 = __expf(m1 - nm1);
        m0 = nm0; m1 = nm1;

        float rs0 = 0.f, rs1 = 0.f;
#pragma unroll
        for (int nb = 0; nb < 8; nb++) {
            s_[nb][0] = __expf(s_[nb][0] - m0);
            s_[nb][1] = __expf(s_[nb][1] - m0);
            s_[nb][2] = __expf(s_[nb][2] - m1);
            s_[nb][3] = __expf(s_[nb][3] - m1);
            rs0 += s_[nb][0] + s_[nb][1];
            rs1 += s_[nb][2] + s_[nb][3];
        }
        rs0 += __shfl_xor_sync(0xffffffffu, rs0, 1);
        rs0 += __shfl_xor_sync(0xffffffffu, rs0, 2);
        rs1 += __shfl_xor_sync(0xffffffffu, rs1, 1);
        rs1 += __shfl_xor_sync(0xffffffffu, rs1, 2);
        l0 = l0 * corr0 + rs0;
        l1 = l1 * corr1 + rs1;

#pragma unroll
        for (int nb = 0; nb < 8; nb++) {
            o[nb][0] *= corr0; o[nb][1] *= corr0;
            o[nb][2] *= corr1; o[nb][3] *= corr1;
        }

        // ---- P to SMEM (own warp's rows only)
#pragma unroll
        for (int nb = 0; nb < 8; nb++) {
            *(float2*)(Ps + (wrow + g) * 68 + nb * 8 + 2 * tig)     = make_float2(s_[nb][0], s_[nb][1]);
            *(float2*)(Ps + (wrow + g + 8) * 68 + nb * 8 + 2 * tig) = make_float2(s_[nb][2], s_[nb][3]);
        }
        __syncwarp();

        // ---- O += P V
#pragma unroll
        for (int ks = 0; ks < 8; ks++) {
            uint32_t pa[4];
            pa[0] = f2tf32(Ps[(wrow + g) * 68 + 8 * ks + tig]);
            pa[1] = f2tf32(Ps[(wrow + g + 8) * 68 + 8 * ks + tig]);
            pa[2] = f2tf32(Ps[(wrow + g) * 68 + 8 * ks + tig + 4]);
            pa[3] = f2tf32(Ps[(wrow + g + 8) * 68 + 8 * ks + tig + 4]);
#pragma unroll
            for (int nb = 0; nb < 8; nb++) {
                int r0 = 8 * ks + tig;
                int cc = nb * 8 + g;
                mma_tf32(o[nb], pa, Vs[r0 * 72 + cc], Vs[(r0 + 4) * 72 + cc]);
            }
        }
        __syncthreads();
    }

    // ---- normalize + store
    float inv0 = 1.0f / l0, inv1 = 1.0f / l1;
    int b = bh / HDS, h = bh % HDS;
    int s0 = qb * 128 + wrow + g;
    int s1 = s0 + 8;
#pragma unroll
    for (int nb = 0; nb < 8; nb++) {
        int cc = nb * 8 + 2 * tig;
        if (s0 < SEQL) {
            float* dst = g_ao + ((size_t)b * SEQL + s0) * EMB + h * HD + cc;
            *(float2*)dst = make_float2(o[nb][0] * inv0, o[nb][1] * inv0);
        }
        if (s1 < SEQL) {
            float* dst = g_ao + ((size_t)b * SEQL + s1) * EMB + h * HD + cc;
            *(float2*)dst = make_float2(o[nb][2] * inv1, o[nb][3] * inv1);
        }
    }
}

// ===================== launch =====================
extern "C" void kernel_launch(void* const* d_in, const int* in_sizes, int n_in,
                              void* d_out, int out_size)
{
    const float* x  = (const float*)d_in[0];
    const float* Wq = (const float*)d_in[1];
    const float* Wk = (const float*)d_in[2];
    const float* Wv = (const float*)d_in[3];
    const float* Wo = (const float*)d_in[4];
    const float* bo = (const float*)d_in[5];
    float* out = (float*)d_out;

    double xg = 2.0;
    for (int it = 0; it < 10; ++it) xg = pow(1.0 + xg, 1.0 / 3.0);
    float inv_g = (float)(1.0 / xg);

    cudaFuncSetAttribute(attn_mma_kernel,
                         cudaFuncAttributeMaxDynamicSharedMemorySize, ATTN_SMEM);
    cudaFuncSetAttribute(qkv_mma_kernel,
                         cudaFuncAttributeMaxDynamicSharedMemorySize, GEMM_SMEM);
    cudaFuncSetAttribute(proj_mma_kernel,
                         cudaFuncAttributeMaxDynamicSharedMemorySize, GEMM_SMEM);

    init_freqs<<<1, 192>>>(inv_g);
    init_trig<<<(SEQL * HDS * NF + 255) / 256, 256>>>();

    dim3 qkv_grid((ROWS + 127) / 128, HDS, 3);
    qkv_mma_kernel<<<qkv_grid, 256, GEMM_SMEM>>>(x, Wq, Wk, Wv);

    dim3 attn_grid(9, BHN);
    attn_mma_kernel<<<attn_grid, 256, ATTN_SMEM>>>();

    dim3 proj_grid((ROWS + 127) / 128, EMB / 64);
    proj_mma_kernel<<<proj_grid, 256, GEMM_SMEM>>>(Wo, bo, out);
}

// round 8
// speedup vs baseline: 2.2165x; 1.0292x over previous
#include <cuda_runtime.h>
#include <math.h>
#include <stdint.h>

#define BB 16
#define SEQL 1025
#define EMB 384
#define HDS 6
#define HD 64
#define NF 32
#define ROWS (BB*SEQL)
#define BHN (BB*HDS)

__device__ float g_q[(size_t)BHN*SEQL*HD];   // [b,h,s,d]
__device__ float g_k[(size_t)BHN*SEQL*HD];
__device__ float g_v[(size_t)BHN*SEQL*HD];
__device__ float g_ao[(size_t)ROWS*EMB];
__device__ float g_cos[SEQL*HDS*NF];
__device__ float g_sin[SEQL*HDS*NF];
__device__ float g_freqs[HDS*NF*2];

// ===================== mma.sync helpers =====================
__device__ __forceinline__ uint32_t f2tf32(float x) {
    uint32_t r;
    asm("cvt.rna.tf32.f32 %0, %1;" : "=r"(r) : "f"(x));
    return r;
}
__device__ __forceinline__ void mma_tf32(float* d, const uint32_t* a,
                                         uint32_t b0, uint32_t b1) {
    asm volatile(
        "mma.sync.aligned.m16n8k8.row.col.f32.tf32.tf32.f32 "
        "{%0,%1,%2,%3}, {%4,%5,%6,%7}, {%8,%9}, {%0,%1,%2,%3};"
        : "+f"(d[0]), "+f"(d[1]), "+f"(d[2]), "+f"(d[3])
        : "r"(a[0]), "r"(a[1]), "r"(a[2]), "r"(a[3]), "r"(b0), "r"(b1));
}

// ===================== init (bit-matched constants) =====================
__device__ __forceinline__ float erfinv_xla(float x) {
    float w = -log1pf(-__fmul_rn(x, x));
    float p;
    if (w < 5.0f) {
        w = w - 2.5f;
        p = 2.81022636e-08f;
        p = fmaf(p, w, 3.43273939e-07f);
        p = fmaf(p, w, -3.5233877e-06f);
        p = fmaf(p, w, -4.39150654e-06f);
        p = fmaf(p, w, 0.00021858087f);
        p = fmaf(p, w, -0.00125372503f);
        p = fmaf(p, w, -0.00417768164f);
        p = fmaf(p, w, 0.246640727f);
        p = fmaf(p, w, 1.50140941f);
    } else {
        w = sqrtf(w) - 3.0f;
        p = -0.000200214257f;
        p = fmaf(p, w, 0.000100950558f);
        p = fmaf(p, w, 0.00134934322f);
        p = fmaf(p, w, -0.00367342844f);
        p = fmaf(p, w, 0.00573950773f);
        p = fmaf(p, w, -0.0076224613f);
        p = fmaf(p, w, 0.00943887047f);
        p = fmaf(p, w, 1.00167406f);
        p = fmaf(p, w, 2.83297682f);
    }
    return p * x;
}

__global__ void init_freqs(float inv_g) {
    int n = threadIdx.x;
    if (n >= HDS * NF) return;
    float alpha0 = powf(inv_g, 1.0f);
    float alpha1 = powf(inv_g, 2.0f);
    float fi = (float)(n + 1);
    float z0 = fmodf(__fmul_rn(fi, alpha0), 1.0f);
    float z1 = fmodf(__fmul_rn(fi, alpha1), 1.0f);
    float d0 = erfinv_xla(__fmul_rn(2.0f, z0) - 1.0f);
    float d1 = erfinv_xla(__fmul_rn(2.0f, z1) - 1.0f);
    float nrm = sqrtf(__fadd_rn(__fmul_rn(d0, d0), __fmul_rn(d1, d1)));
    d0 = __fdiv_rn(d0, nrm);
    d1 = __fdiv_rn(d1, nrm);
    int f = n % NF;
    float t = __fmul_rn((float)f, (1.0f / 31.0f));
    float omega = __fmul_rn(0.1f, powf(10000.0f, t));
    g_freqs[n * 2 + 0] = __fmul_rn(d0, omega);
    g_freqs[n * 2 + 1] = __fmul_rn(d1, omega);
}

__global__ void init_trig() {
    int idx = blockIdx.x * blockDim.x + threadIdx.x;
    if (idx >= SEQL * HDS * NF) return;
    int s = idx / (HDS * NF);
    int r = idx % (HDS * NF);
    float c0 = 0.f, c1 = 0.f;
    if (s > 0) {
        int p = s - 1;
        int xi = p % 32, yi = p / 32;
        c0 = __fmul_rn(__fdiv_rn((float)xi, 31.0f), 2.0f) - 1.0f;
        c1 = __fmul_rn(__fdiv_rn((float)yi, 31.0f), 2.0f) - 1.0f;
    }
    float th = __fadd_rn(__fmul_rn(g_freqs[r * 2 + 0], c0), __fmul_rn(g_freqs[r * 2 + 1], c1));
    g_cos[idx] = cosf(th);
    g_sin[idx] = sinf(th);
}

// ===================== tensorized GEMM: QKV (+RoPE) and proj (+bias) ========
#define GW_OFF 8704
#define GEMM_SMEM ((8704 + 9216) * 4)   // 71680 B

struct GemmAcc { float o[8][4]; };

__device__ __forceinline__ void gemm_core_128x64(
    const float* __restrict__ src,
    const float* __restrict__ W, int colbase,
    int row0, float* xs, uint4* Wp, GemmAcc& A)
{
    int tid = threadIdx.x;
    int wid = tid >> 5, lane = tid & 31;
    int g = lane >> 2, tig = lane & 3;
    int wrow = wid * 16;

    for (int c = 0; c < 6; c++) {
        int k0 = c * 64;
#pragma unroll
        for (int u = 0; u < 8; u++) {
            int idx = tid + 256 * u;
            int rr = idx >> 4, c4 = idx & 15;
            int gr = row0 + rr;
            float4 v = make_float4(0.f, 0.f, 0.f, 0.f);
            if (gr < ROWS) v = *(const float4*)(src + (size_t)gr * EMB + k0 + 4 * c4);
            *(float4*)(xs + rr * 68 + 4 * c4) = v;
        }
#pragma unroll
        for (int u = 0; u < 2; u++) {
            int id = tid + 256 * u;
            int n = id & 63, ks = id >> 6;
            float wv[8];
#pragma unroll
            for (int j = 0; j < 8; j++)
                wv[j] = W[(size_t)(k0 + 8 * ks + j) * EMB + colbase + n];
            uint32_t hi[8], lo[8];
#pragma unroll
            for (int j = 0; j < 8; j++) {
                hi[j] = f2tf32(wv[j]);
                lo[j] = f2tf32(wv[j] - __uint_as_float(hi[j]));
            }
            uint4* dst = Wp + n * 36 + ks * 4;
            dst[0] = make_uint4(hi[0], hi[4], lo[0], lo[4]);
            dst[1] = make_uint4(hi[1], hi[5], lo[1], lo[5]);
            dst[2] = make_uint4(hi[2], hi[6], lo[2], lo[6]);
            dst[3] = make_uint4(hi[3], hi[7], lo[3], lo[7]);
        }
        __syncthreads();

#pragma unroll
        for (int ks = 0; ks < 8; ks++) {
            float a0 = xs[(wrow + g) * 68 + 8 * ks + tig];
            float a1 = xs[(wrow + g + 8) * 68 + 8 * ks + tig];
            float a2 = xs[(wrow + g) * 68 + 8 * ks + tig + 4];
            float a3 = xs[(wrow + g + 8) * 68 + 8 * ks + tig + 4];
            uint32_t ahi[4], alo[4];
            ahi[0] = f2tf32(a0); alo[0] = f2tf32(a0 - __uint_as_float(ahi[0]));
            ahi[1] = f2tf32(a1); alo[1] = f2tf32(a1 - __uint_as_float(ahi[1]));
            ahi[2] = f2tf32(a2); alo[2] = f2tf32(a2 - __uint_as_float(ahi[2]));
            ahi[3] = f2tf32(a3); alo[3] = f2tf32(a3 - __uint_as_float(ahi[3]));
#pragma unroll
            for (int nb = 0; nb < 8; nb++) {
                uint4 w4 = Wp[(nb * 8 + g) * 36 + ks * 4 + tig];
                mma_tf32(A.o[nb], ahi, w4.x, w4.y);
                mma_tf32(A.o[nb], ahi, w4.z, w4.w);
                mma_tf32(A.o[nb], alo, w4.x, w4.y);
            }
        }
        __syncthreads();
    }
}

__global__ void __launch_bounds__(256) qkv_mma_kernel(
    const float* __restrict__ x, const float* __restrict__ Wq,
    const float* __restrict__ Wk, const float* __restrict__ Wv)
{
    extern __shared__ float sm[];
    float* xs = sm;
    uint4* Wp = (uint4*)(sm + GW_OFF);

    int tid = threadIdx.x;
    int wid = tid >> 5, lane = tid & 31;
    int g = lane >> 2, tig = lane & 3;
    int wrow = wid * 16;
    int rb = blockIdx.x, h = blockIdx.y, z = blockIdx.z;
    const float* W = (z == 0) ? Wq : ((z == 1) ? Wk : Wv);
    int row0 = rb * 128;

    GemmAcc A;
#pragma unroll
    for (int nb = 0; nb < 8; nb++)
#pragma unroll
        for (int j = 0; j < 4; j++) A.o[nb][j] = 0.f;

    gemm_core_128x64(x, W, h * 64, row0, xs, Wp, A);

    if (z < 2) {
        float* base = (z == 0) ? g_q : g_k;
#pragma unroll
        for (int nb = 0; nb < 4; nb++)
#pragma unroll
            for (int jj = 0; jj < 4; jj++) {
                int gr = row0 + wrow + g + 8 * (jj >> 1);
                if (gr >= ROWS) continue;
                int b = gr / SEQL, s = gr % SEQL;
                int f = 8 * nb + 2 * tig + (jj & 1);
                float cv = g_cos[(s * HDS + h) * NF + f];
                float sv = g_sin[(s * HDS + h) * NF + f];
                float lov = A.o[nb][jj], hiv = A.o[nb + 4][jj];
                float* dst = base + ((size_t)(b * HDS + h) * SEQL + s) * HD;
                dst[f]      = lov * cv - hiv * sv;
                dst[f + 32] = lov * sv + hiv * cv;
            }
    } else {
#pragma unroll
        for (int nb = 0; nb < 8; nb++)
#pragma unroll
            for (int jj = 0; jj < 4; jj++) {
                int gr = row0 + wrow + g + 8 * (jj >> 1);
                if (gr >= ROWS) continue;
                int b = gr / SEQL, s = gr % SEQL;
                int col = 8 * nb + 2 * tig + (jj & 1);
                g_v[((size_t)(b * HDS + h) * SEQL + s) * HD + col] = A.o[nb][jj];
            }
    }
}

__global__ void __launch_bounds__(256) proj_mma_kernel(
    const float* __restrict__ Wo, const float* __restrict__ bo,
    float* __restrict__ out)
{
    extern __shared__ float sm[];
    float* xs = sm;
    uint4* Wp = (uint4*)(sm + GW_OFF);

    int tid = threadIdx.x;
    int wid = tid >> 5, lane = tid & 31;
    int g = lane >> 2, tig = lane & 3;
    int wrow = wid * 16;
    int rb = blockIdx.x, cb = blockIdx.y;
    int row0 = rb * 128, colbase = cb * 64;

    GemmAcc A;
#pragma unroll
    for (int nb = 0; nb < 8; nb++)
#pragma unroll
        for (int j = 0; j < 4; j++) A.o[nb][j] = 0.f;

    gemm_core_128x64(g_ao, Wo, colbase, row0, xs, Wp, A);

#pragma unroll
    for (int nb = 0; nb < 8; nb++)
#pragma unroll
        for (int jj = 0; jj < 4; jj++) {
            int gr = row0 + wrow + g + 8 * (jj >> 1);
            if (gr >= ROWS) continue;
            int col = 8 * nb + 2 * tig + (jj & 1);
            out[(size_t)gr * EMB + colbase + col] = A.o[nb][jj] + bo[colbase + col];
        }
}

// ===================== Flash attention (BM=64, 128 thr, 3 CTAs/SM) ==========
// word offsets: Ps [64][68]=4352 | Kp 64*36 uint2=4608 | Vs [64][72]=4608
#define PS_OFF 0
#define KP_OFF 4352
#define VS_OFF 8960
#define ATTN_SMEM (13568 * 4)   // 54272 B

__global__ void __launch_bounds__(128, 3) attn_mma_kernel() {
    extern __shared__ float sm[];
    float*    Ps = sm + PS_OFF;
    uint2*    Kp = (uint2*)(sm + KP_OFF);
    uint32_t* Vs = (uint32_t*)(sm + VS_OFF);

    int tid = threadIdx.x;
    int wid = tid >> 5, lane = tid & 31;
    int g = lane >> 2, tig = lane & 3;
    int wrow = wid * 16;
    int qb = blockIdx.x, bh = blockIdx.y;

    const float* Q = g_q + (size_t)bh * SEQL * HD;
    const float* K = g_k + (size_t)bh * SEQL * HD;
    const float* V = g_v + (size_t)bh * SEQL * HD;

    // ---- stage Q (scaled 1/8): 64 rows
#pragma unroll
    for (int u = 0; u < 8; u++) {
        int idx = tid + 128 * u;
        int rr = idx >> 4, c4 = idx & 15;
        int s = qb * 64 + rr;
        float4 v = make_float4(0.f, 0.f, 0.f, 0.f);
        if (s < SEQL) v = *(const float4*)(Q + (size_t)s * HD + c4 * 4);
        v.x *= 0.125f; v.y *= 0.125f; v.z *= 0.125f; v.w *= 0.125f;
        *(float4*)(Ps + rr * 68 + c4 * 4) = v;
    }
    __syncthreads();

    uint32_t qhi[8][4];
#pragma unroll
    for (int ks = 0; ks < 8; ks++) {
#pragma unroll
        for (int j = 0; j < 4; j++) {
            int rr = wrow + g + (j & 1) * 8;
            int cc = 8 * ks + tig + (j >> 1) * 4;
            qhi[ks][j] = f2tf32(Ps[rr * 68 + cc]);
        }
    }
    __syncthreads();

    float o[8][4] = {};
    float m0 = -INFINITY, m1 = -INFINITY, l0 = 0.f, l1 = 0.f;

    for (int t = 0; t < 17; t++) {
        // ---- K pack (rotated stores)
#pragma unroll
        for (int u = 0; u < 4; u++) {
            int id = tid + 128 * u;
            int n = id >> 3, ks = id & 7;
            int s = t * 64 + n;
            float4 ka = make_float4(0.f, 0.f, 0.f, 0.f);
            float4 kb = make_float4(0.f, 0.f, 0.f, 0.f);
            if (s < SEQL) {
                ka = *(const float4*)(K + (size_t)s * HD + 8 * ks);
                kb = *(const float4*)(K + (size_t)s * HD + 8 * ks + 4);
            }
            uint32_t hi[8];
            hi[0] = f2tf32(ka.x); hi[1] = f2tf32(ka.y);
            hi[2] = f2tf32(ka.z); hi[3] = f2tf32(ka.w);
            hi[4] = f2tf32(kb.x); hi[5] = f2tf32(kb.y);
            hi[6] = f2tf32(kb.z); hi[7] = f2tf32(kb.w);
            int rot = ((ks >> 2) + 2 * (n & 1)) & 3;
            uint2* dst = Kp + n * 36 + ks * 4;
#pragma unroll
            for (int tt = 0; tt < 4; tt++) {
                int tg = (tt + rot) & 3;
                dst[tg] = make_uint2(hi[tg], hi[tg + 4]);
            }
        }
        // ---- V stage, pre-converted tf32
#pragma unroll
        for (int u = 0; u < 8; u++) {
            int idx = tid + 128 * u;
            int rr = idx >> 4, c4 = idx & 15;
            int s = t * 64 + rr;
            float4 v = make_float4(0.f, 0.f, 0.f, 0.f);
            if (s < SEQL) v = *(const float4*)(V + (size_t)s * HD + 4 * c4);
            uint4 vh = make_uint4(f2tf32(v.x), f2tf32(v.y), f2tf32(v.z), f2tf32(v.w));
            *(uint4*)(Vs + rr * 72 + c4 * 4) = vh;
        }
        __syncthreads();

        // ---- S = Q K^T, single tf32 pass
        float s_[8][4] = {};
#pragma unroll
        for (int ks = 0; ks < 8; ks++) {
#pragma unroll
            for (int nb = 0; nb < 8; nb++) {
                uint2 kk = Kp[(nb * 8 + g) * 36 + ks * 4 + tig];
                mma_tf32(s_[nb], qhi[ks], kk.x, kk.y);
            }
        }

        if (t == 16) {
#pragma unroll
            for (int nb = 0; nb < 8; nb++) {
                int c = 1024 + nb * 8 + 2 * tig;
                if (c >= SEQL)     { s_[nb][0] = -INFINITY; s_[nb][2] = -INFINITY; }
                if (c + 1 >= SEQL) { s_[nb][1] = -INFINITY; s_[nb][3] = -INFINITY; }
            }
        }

        // ---- online softmax
        float rm0 = -INFINITY, rm1 = -INFINITY;
#pragma unroll
        for (int nb = 0; nb < 8; nb++) {
            rm0 = fmaxf(rm0, fmaxf(s_[nb][0], s_[nb][1]));
            rm1 = fmaxf(rm1, fmaxf(s_[nb][2], s_[nb][3]));
        }
        rm0 = fmaxf(rm0, __shfl_xor_sync(0xffffffffu, rm0, 1));
        rm0 = fmaxf(rm0, __shfl_xor_sync(0xffffffffu, rm0, 2));
        rm1 = fmaxf(rm1, __shfl_xor_sync(0xffffffffu, rm1, 1));
        rm1 = fmaxf(rm1, __shfl_xor_sync(0xffffffffu, rm1, 2));
        float nm0 = fmaxf(m0, rm0), nm1 = fmaxf(m1, rm1);
        float corr0 = __expf(m0 - nm0), corr1 = __expf(m1 - nm1);
        m0 = nm0; m1 = nm1;

        float rs0 = 0.f, rs1 = 0.f;
#pragma unroll
        for (int nb = 0; nb < 8; nb++) {
            s_[nb][0] = __expf(s_[nb][0] - m0);
            s_[nb][1] = __expf(s_[nb][1] - m0);
            s_[nb][2] = __expf(s_[nb][2] - m1);
            s_[nb][3] = __expf(s_[nb][3] - m1);
            rs0 += s_[nb][0] + s_[nb][1];
            rs1 += s_[nb][2] + s_[nb][3];
        }
        rs0 += __shfl_xor_sync(0xffffffffu, rs0, 1);
        rs0 += __shfl_xor_sync(0xffffffffu, rs0, 2);
        rs1 += __shfl_xor_sync(0xffffffffu, rs1, 1);
        rs1 += __shfl_xor_sync(0xffffffffu, rs1, 2);
        l0 = l0 * corr0 + rs0;
        l1 = l1 * corr1 + rs1;

#pragma unroll
        for (int nb = 0; nb < 8; nb++) {
            o[nb][0] *= corr0; o[nb][1] *= corr0;
            o[nb][2] *= corr1; o[nb][3] *= corr1;
        }

        // ---- P to SMEM (own warp's rows only)
#pragma unroll
        for (int nb = 0; nb < 8; nb++) {
            *(float2*)(Ps + (wrow + g) * 68 + nb * 8 + 2 * tig)     = make_float2(s_[nb][0], s_[nb][1]);
            *(float2*)(Ps + (wrow + g + 8) * 68 + nb * 8 + 2 * tig) = make_float2(s_[nb][2], s_[nb][3]);
        }
        __syncwarp();

        // ---- O += P V
#pragma unroll
        for (int ks = 0; ks < 8; ks++) {
            uint32_t pa[4];
            pa[0] = f2tf32(Ps[(wrow + g) * 68 + 8 * ks + tig]);
            pa[1] = f2tf32(Ps[(wrow + g + 8) * 68 + 8 * ks + tig]);
            pa[2] = f2tf32(Ps[(wrow + g) * 68 + 8 * ks + tig + 4]);
            pa[3] = f2tf32(Ps[(wrow + g + 8) * 68 + 8 * ks + tig + 4]);
#pragma unroll
            for (int nb = 0; nb < 8; nb++) {
                int r0 = 8 * ks + tig;
                int cc = nb * 8 + g;
                mma_tf32(o[nb], pa, Vs[r0 * 72 + cc], Vs[(r0 + 4) * 72 + cc]);
            }
        }
        __syncthreads();
    }

    // ---- normalize + store
    float inv0 = 1.0f / l0, inv1 = 1.0f / l1;
    int b = bh / HDS, h = bh % HDS;
    int s0 = qb * 64 + wrow + g;
    int s1 = s0 + 8;
#pragma unroll
    for (int nb = 0; nb < 8; nb++) {
        int cc = nb * 8 + 2 * tig;
        if (s0 < SEQL) {
            float* dst = g_ao + ((size_t)b * SEQL + s0) * EMB + h * HD + cc;
            *(float2*)dst = make_float2(o[nb][0] * inv0, o[nb][1] * inv0);
        }
        if (s1 < SEQL) {
            float* dst = g_ao + ((size_t)b * SEQL + s1) * EMB + h * HD + cc;
            *(float2*)dst = make_float2(o[nb][2] * inv1, o[nb][3] * inv1);
        }
    }
}

// ===================== launch =====================
extern "C" void kernel_launch(void* const* d_in, const int* in_sizes, int n_in,
                              void* d_out, int out_size)
{
    const float* x  = (const float*)d_in[0];
    const float* Wq = (const float*)d_in[1];
    const float* Wk = (const float*)d_in[2];
    const float* Wv = (const float*)d_in[3];
    const float* Wo = (const float*)d_in[4];
    const float* bo = (const float*)d_in[5];
    float* out = (float*)d_out;

    double xg = 2.0;
    for (int it = 0; it < 10; ++it) xg = pow(1.0 + xg, 1.0 / 3.0);
    float inv_g = (float)(1.0 / xg);

    cudaFuncSetAttribute(attn_mma_kernel,
                         cudaFuncAttributeMaxDynamicSharedMemorySize, ATTN_SMEM);
    cudaFuncSetAttribute(qkv_mma_kernel,
                         cudaFuncAttributeMaxDynamicSharedMemorySize, GEMM_SMEM);
    cudaFuncSetAttribute(proj_mma_kernel,
                         cudaFuncAttributeMaxDynamicSharedMemorySize, GEMM_SMEM);

    init_freqs<<<1, 192>>>(inv_g);
    init_trig<<<(SEQL * HDS * NF + 255) / 256, 256>>>();

    dim3 qkv_grid((ROWS + 127) / 128, HDS, 3);
    qkv_mma_kernel<<<qkv_grid, 256, GEMM_SMEM>>>(x, Wq, Wk, Wv);

    dim3 attn_grid(17, BHN);
    attn_mma_kernel<<<attn_grid, 128, ATTN_SMEM>>>();

    dim3 proj_grid((ROWS + 127) / 128, EMB / 64);
    proj_mma_kernel<<<proj_grid, 256, GEMM_SMEM>>>(Wo, bo, out);
}

// round 9
// speedup vs baseline: 2.7418x; 1.2370x over previous
#include <cuda_runtime.h>
#include <math.h>
#include <stdint.h>

#define BB 16
#define SEQL 1025
#define EMB 384
#define HDS 6
#define HD 64
#define NF 32
#define ROWS (BB*SEQL)
#define BHN (BB*HDS)
#define NT 17            // kv tiles of 64
#define NPAD (NT*64)     // 1088

__device__ float g_q[(size_t)BHN*SEQL*HD];   // [b,h,s,d]
__device__ float g_k[(size_t)BHN*SEQL*HD];
__device__ float g_v[(size_t)BHN*SEQL*HD];
__device__ float g_ao[(size_t)ROWS*EMB];
__device__ float g_cos[SEQL*HDS*NF];
__device__ float g_sin[SEQL*HDS*NF];
__device__ float g_freqs[HDS*NF*2];
// packed K fragments: [bh][t][n*36 + ks*4 + tig] = (tf32 K[n][8ks+tig], tf32 K[n][8ks+tig+4])
__device__ uint2    g_kp[(size_t)BHN*NT*2304];
// padded tf32 V: [bh][t][r*72 + c], c<64 data, c>=64 zero
__device__ uint32_t g_vp[(size_t)BHN*NT*4608];

// ===================== mma.sync helpers =====================
__device__ __forceinline__ uint32_t f2tf32(float x) {
    uint32_t r;
    asm("cvt.rna.tf32.f32 %0, %1;" : "=r"(r) : "f"(x));
    return r;
}
__device__ __forceinline__ void mma_tf32(float* d, const uint32_t* a,
                                         uint32_t b0, uint32_t b1) {
    asm volatile(
        "mma.sync.aligned.m16n8k8.row.col.f32.tf32.tf32.f32 "
        "{%0,%1,%2,%3}, {%4,%5,%6,%7}, {%8,%9}, {%0,%1,%2,%3};"
        : "+f"(d[0]), "+f"(d[1]), "+f"(d[2]), "+f"(d[3])
        : "r"(a[0]), "r"(a[1]), "r"(a[2]), "r"(a[3]), "r"(b0), "r"(b1));
}
__device__ __forceinline__ uint32_t smem_to_u32(const void* p) {
    uint32_t a;
    asm("{ .reg .u64 t; cvta.to.shared.u64 t, %1; cvt.u32.u64 %0, t; }" : "=r"(a) : "l"(p));
    return a;
}
#define CP16(dst, src) \
    asm volatile("cp.async.cg.shared.global [%0], [%1], 16;" :: "r"(dst), "l"(src))
#define CP_COMMIT() asm volatile("cp.async.commit_group;" ::: "memory")
#define CP_WAIT0()  asm volatile("cp.async.wait_group 0;" ::: "memory")

// ===================== init (bit-matched constants) =====================
__device__ __forceinline__ float erfinv_xla(float x) {
    float w = -log1pf(-__fmul_rn(x, x));
    float p;
    if (w < 5.0f) {
        w = w - 2.5f;
        p = 2.81022636e-08f;
        p = fmaf(p, w, 3.43273939e-07f);
        p = fmaf(p, w, -3.5233877e-06f);
        p = fmaf(p, w, -4.39150654e-06f);
        p = fmaf(p, w, 0.00021858087f);
        p = fmaf(p, w, -0.00125372503f);
        p = fmaf(p, w, -0.00417768164f);
        p = fmaf(p, w, 0.246640727f);
        p = fmaf(p, w, 1.50140941f);
    } else {
        w = sqrtf(w) - 3.0f;
        p = -0.000200214257f;
        p = fmaf(p, w, 0.000100950558f);
        p = fmaf(p, w, 0.00134934322f);
        p = fmaf(p, w, -0.00367342844f);
        p = fmaf(p, w, 0.00573950773f);
        p = fmaf(p, w, -0.0076224613f);
        p = fmaf(p, w, 0.00943887047f);
        p = fmaf(p, w, 1.00167406f);
        p = fmaf(p, w, 2.83297682f);
    }
    return p * x;
}

__global__ void init_freqs(float inv_g) {
    int n = threadIdx.x;
    if (n >= HDS * NF) return;
    float alpha0 = powf(inv_g, 1.0f);
    float alpha1 = powf(inv_g, 2.0f);
    float fi = (float)(n + 1);
    float z0 = fmodf(__fmul_rn(fi, alpha0), 1.0f);
    float z1 = fmodf(__fmul_rn(fi, alpha1), 1.0f);
    float d0 = erfinv_xla(__fmul_rn(2.0f, z0) - 1.0f);
    float d1 = erfinv_xla(__fmul_rn(2.0f, z1) - 1.0f);
    float nrm = sqrtf(__fadd_rn(__fmul_rn(d0, d0), __fmul_rn(d1, d1)));
    d0 = __fdiv_rn(d0, nrm);
    d1 = __fdiv_rn(d1, nrm);
    int f = n % NF;
    float t = __fmul_rn((float)f, (1.0f / 31.0f));
    float omega = __fmul_rn(0.1f, powf(10000.0f, t));
    g_freqs[n * 2 + 0] = __fmul_rn(d0, omega);
    g_freqs[n * 2 + 1] = __fmul_rn(d1, omega);
}

__global__ void init_trig() {
    int idx = blockIdx.x * blockDim.x + threadIdx.x;
    if (idx >= SEQL * HDS * NF) return;
    int s = idx / (HDS * NF);
    int r = idx % (HDS * NF);
    float c0 = 0.f, c1 = 0.f;
    if (s > 0) {
        int p = s - 1;
        int xi = p % 32, yi = p / 32;
        c0 = __fmul_rn(__fdiv_rn((float)xi, 31.0f), 2.0f) - 1.0f;
        c1 = __fmul_rn(__fdiv_rn((float)yi, 31.0f), 2.0f) - 1.0f;
    }
    float th = __fadd_rn(__fmul_rn(g_freqs[r * 2 + 0], c0), __fmul_rn(g_freqs[r * 2 + 1], c1));
    g_cos[idx] = cosf(th);
    g_sin[idx] = sinf(th);
}

// ===================== one-shot pack kernels =====================
__global__ void __launch_bounds__(256) pack_k_kernel() {
    int idx = blockIdx.x * 256 + threadIdx.x;
    if (idx >= BHN * NPAD * 8) return;
    int ks = idx & 7;
    int tmp = idx >> 3;
    int n = tmp % NPAD;
    int bh = tmp / NPAD;
    float4 ka = make_float4(0.f, 0.f, 0.f, 0.f);
    float4 kb = make_float4(0.f, 0.f, 0.f, 0.f);
    if (n < SEQL) {
        const float* K = g_k + ((size_t)bh * SEQL + n) * HD + 8 * ks;
        ka = *(const float4*)K;
        kb = *(const float4*)(K + 4);
    }
    uint2* dst = g_kp + ((size_t)bh * NT + (n >> 6)) * 2304 + (n & 63) * 36 + ks * 4;
    dst[0] = make_uint2(f2tf32(ka.x), f2tf32(kb.x));
    dst[1] = make_uint2(f2tf32(ka.y), f2tf32(kb.y));
    dst[2] = make_uint2(f2tf32(ka.z), f2tf32(kb.z));
    dst[3] = make_uint2(f2tf32(ka.w), f2tf32(kb.w));
}

__global__ void __launch_bounds__(256) pack_v_kernel() {
    int idx = blockIdx.x * 256 + threadIdx.x;
    if (idx >= BHN * NPAD * 18) return;
    int c4 = idx % 18;
    int tmp = idx / 18;
    int n = tmp % NPAD;
    int bh = tmp / NPAD;
    uint4 val = make_uint4(0u, 0u, 0u, 0u);
    if (c4 < 16 && n < SEQL) {
        float4 v = *(const float4*)(g_v + ((size_t)bh * SEQL + n) * HD + 4 * c4);
        val = make_uint4(f2tf32(v.x), f2tf32(v.y), f2tf32(v.z), f2tf32(v.w));
    }
    *(uint4*)(g_vp + ((size_t)bh * NT + (n >> 6)) * 4608 + (n & 63) * 72 + c4 * 4) = val;
}

// ===================== tensorized GEMM: QKV (+RoPE) and proj (+bias) ========
#define GW_OFF 8704
#define GEMM_SMEM ((8704 + 9216) * 4)   // 71680 B

struct GemmAcc { float o[8][4]; };

__device__ __forceinline__ void gemm_core_128x64(
    const float* __restrict__ src,
    const float* __restrict__ W, int colbase,
    int row0, float* xs, uint4* Wp, GemmAcc& A)
{
    int tid = threadIdx.x;
    int wid = tid >> 5, lane = tid & 31;
    int g = lane >> 2, tig = lane & 3;
    int wrow = wid * 16;

    for (int c = 0; c < 6; c++) {
        int k0 = c * 64;
#pragma unroll
        for (int u = 0; u < 8; u++) {
            int idx = tid + 256 * u;
            int rr = idx >> 4, c4 = idx & 15;
            int gr = row0 + rr;
            float4 v = make_float4(0.f, 0.f, 0.f, 0.f);
            if (gr < ROWS) v = *(const float4*)(src + (size_t)gr * EMB + k0 + 4 * c4);
            *(float4*)(xs + rr * 68 + 4 * c4) = v;
        }
#pragma unroll
        for (int u = 0; u < 2; u++) {
            int id = tid + 256 * u;
            int n = id & 63, ks = id >> 6;
            float wv[8];
#pragma unroll
            for (int j = 0; j < 8; j++)
                wv[j] = W[(size_t)(k0 + 8 * ks + j) * EMB + colbase + n];
            uint32_t hi[8], lo[8];
#pragma unroll
            for (int j = 0; j < 8; j++) {
                hi[j] = f2tf32(wv[j]);
                lo[j] = f2tf32(wv[j] - __uint_as_float(hi[j]));
            }
            uint4* dst = Wp + n * 36 + ks * 4;
            dst[0] = make_uint4(hi[0], hi[4], lo[0], lo[4]);
            dst[1] = make_uint4(hi[1], hi[5], lo[1], lo[5]);
            dst[2] = make_uint4(hi[2], hi[6], lo[2], lo[6]);
            dst[3] = make_uint4(hi[3], hi[7], lo[3], lo[7]);
        }
        __syncthreads();

#pragma unroll
        for (int ks = 0; ks < 8; ks++) {
            float a0 = xs[(wrow + g) * 68 + 8 * ks + tig];
            float a1 = xs[(wrow + g + 8) * 68 + 8 * ks + tig];
            float a2 = xs[(wrow + g) * 68 + 8 * ks + tig + 4];
            float a3 = xs[(wrow + g + 8) * 68 + 8 * ks + tig + 4];
            uint32_t ahi[4], alo[4];
            ahi[0] = f2tf32(a0); alo[0] = f2tf32(a0 - __uint_as_float(ahi[0]));
            ahi[1] = f2tf32(a1); alo[1] = f2tf32(a1 - __uint_as_float(ahi[1]));
            ahi[2] = f2tf32(a2); alo[2] = f2tf32(a2 - __uint_as_float(ahi[2]));
            ahi[3] = f2tf32(a3); alo[3] = f2tf32(a3 - __uint_as_float(ahi[3]));
#pragma unroll
            for (int nb = 0; nb < 8; nb++) {
                uint4 w4 = Wp[(nb * 8 + g) * 36 + ks * 4 + tig];
                mma_tf32(A.o[nb], ahi, w4.x, w4.y);
                mma_tf32(A.o[nb], ahi, w4.z, w4.w);
                mma_tf32(A.o[nb], alo, w4.x, w4.y);
            }
        }
        __syncthreads();
    }
}

__global__ void __launch_bounds__(256) qkv_mma_kernel(
    const float* __restrict__ x, const float* __restrict__ Wq,
    const float* __restrict__ Wk, const float* __restrict__ Wv)
{
    extern __shared__ float sm[];
    float* xs = sm;
    uint4* Wp = (uint4*)(sm + GW_OFF);

    int tid = threadIdx.x;
    int wid = tid >> 5, lane = tid & 31;
    int g = lane >> 2, tig = lane & 3;
    int wrow = wid * 16;
    int rb = blockIdx.x, h = blockIdx.y, z = blockIdx.z;
    const float* W = (z == 0) ? Wq : ((z == 1) ? Wk : Wv);
    int row0 = rb * 128;

    GemmAcc A;
#pragma unroll
    for (int nb = 0; nb < 8; nb++)
#pragma unroll
        for (int j = 0; j < 4; j++) A.o[nb][j] = 0.f;

    gemm_core_128x64(x, W, h * 64, row0, xs, Wp, A);

    if (z < 2) {
        float* base = (z == 0) ? g_q : g_k;
#pragma unroll
        for (int nb = 0; nb < 4; nb++)
#pragma unroll
            for (int jj = 0; jj < 4; jj++) {
                int gr = row0 + wrow + g + 8 * (jj >> 1);
                if (gr >= ROWS) continue;
                int b = gr / SEQL, s = gr % SEQL;
                int f = 8 * nb + 2 * tig + (jj & 1);
                float cv = g_cos[(s * HDS + h) * NF + f];
                float sv = g_sin[(s * HDS + h) * NF + f];
                float lov = A.o[nb][jj], hiv = A.o[nb + 4][jj];
                float* dst = base + ((size_t)(b * HDS + h) * SEQL + s) * HD;
                dst[f]      = lov * cv - hiv * sv;
                dst[f + 32] = lov * sv + hiv * cv;
            }
    } else {
#pragma unroll
        for (int nb = 0; nb < 8; nb++)
#pragma unroll
            for (int jj = 0; jj < 4; jj++) {
                int gr = row0 + wrow + g + 8 * (jj >> 1);
                if (gr >= ROWS) continue;
                int b = gr / SEQL, s = gr % SEQL;
                int col = 8 * nb + 2 * tig + (jj & 1);
                g_v[((size_t)(b * HDS + h) * SEQL + s) * HD + col] = A.o[nb][jj];
            }
    }
}

__global__ void __launch_bounds__(256) proj_mma_kernel(
    const float* __restrict__ Wo, const float* __restrict__ bo,
    float* __restrict__ out)
{
    extern __shared__ float sm[];
    float* xs = sm;
    uint4* Wp = (uint4*)(sm + GW_OFF);

    int tid = threadIdx.x;
    int wid = tid >> 5, lane = tid & 31;
    int g = lane >> 2, tig = lane & 3;
    int wrow = wid * 16;
    int rb = blockIdx.x, cb = blockIdx.y;
    int row0 = rb * 128, colbase = cb * 64;

    GemmAcc A;
#pragma unroll
    for (int nb = 0; nb < 8; nb++)
#pragma unroll
        for (int j = 0; j < 4; j++) A.o[nb][j] = 0.f;

    gemm_core_128x64(g_ao, Wo, colbase, row0, xs, Wp, A);

#pragma unroll
    for (int nb = 0; nb < 8; nb++)
#pragma unroll
        for (int jj = 0; jj < 4; jj++) {
            int gr = row0 + wrow + g + 8 * (jj >> 1);
            if (gr >= ROWS) continue;
            int col = 8 * nb + 2 * tig + (jj & 1);
            out[(size_t)gr * EMB + colbase + col] = A.o[nb][jj] + bo[colbase + col];
        }
}

// ===================== Flash attention (cp.async pipelined) =================
// words: Ps [64][68]=4352 | Kp 4608 (single buf) | V 2x4608
#define PS_OFF 0
#define KP_OFF 4352
#define V0_OFF 8960
#define V1_OFF 13568
#define ATTN_SMEM (18176 * 4)   // 72704 B

__global__ void __launch_bounds__(128, 3) attn_mma_kernel() {
    extern __shared__ float sm[];
    float* Ps = sm + PS_OFF;
    uint32_t sbase = smem_to_u32(sm);

    int tid = threadIdx.x;
    int wid = tid >> 5, lane = tid & 31;
    int g = lane >> 2, tig = lane & 3;
    int wrow = wid * 16;
    int qb = blockIdx.x, bh = blockIdx.y;

    const float* Q = g_q + (size_t)bh * SEQL * HD;
    const char* gk = (const char*)(g_kp + (size_t)bh * NT * 2304);
    const char* gv = (const char*)(g_vp + (size_t)bh * NT * 4608);

    const uint32_t KPA = sbase + KP_OFF * 4;
    const uint32_t VA[2] = { sbase + V0_OFF * 4, sbase + V1_OFF * 4 };

    // prefetch K(0) + V(0)
#pragma unroll
    for (int i = 0; i < 9; i++) {
        int off = (tid + 128 * i) * 16;
        CP16(KPA + off, gk + off);
        CP16(VA[0] + off, gv + off);
    }
    CP_COMMIT();

    // ---- stage Q (scaled 1/8)
#pragma unroll
    for (int u = 0; u < 8; u++) {
        int idx = tid + 128 * u;
        int rr = idx >> 4, c4 = idx & 15;
        int s = qb * 64 + rr;
        float4 v = make_float4(0.f, 0.f, 0.f, 0.f);
        if (s < SEQL) v = *(const float4*)(Q + (size_t)s * HD + c4 * 4);
        v.x *= 0.125f; v.y *= 0.125f; v.z *= 0.125f; v.w *= 0.125f;
        *(float4*)(Ps + rr * 68 + c4 * 4) = v;
    }
    __syncthreads();

    uint32_t qhi[8][4];
#pragma unroll
    for (int ks = 0; ks < 8; ks++) {
#pragma unroll
        for (int j = 0; j < 4; j++) {
            int rr = wrow + g + (j & 1) * 8;
            int cc = 8 * ks + tig + (j >> 1) * 4;
            qhi[ks][j] = f2tf32(Ps[rr * 68 + cc]);
        }
    }
    // NOTE: no barrier needed here before P writes: first P write happens
    // after the tile-0 top barrier below.

    float o[8][4] = {};
    float m0 = -INFINITY, m1 = -INFINITY, l0 = 0.f, l1 = 0.f;

    for (int t = 0; t < NT; t++) {
        CP_WAIT0();
        __syncthreads();   // K(t), V(t) visible; all PV(t-1) reads done

        // prefetch V(t+1) into the buffer V(t-1) occupied
        if (t < NT - 1) {
            const char* vsrc = gv + (size_t)(t + 1) * 4608 * 4;
            uint32_t vdst = VA[(t + 1) & 1];
#pragma unroll
            for (int i = 0; i < 9; i++) {
                int off = (tid + 128 * i) * 16;
                CP16(vdst + off, vsrc + off);
            }
            CP_COMMIT();
        }

        // ---- S = Q K^T (single tf32 pass)
        uint2* Kp = (uint2*)(sm + KP_OFF);
        float s_[8][4] = {};
#pragma unroll
        for (int ks = 0; ks < 8; ks++) {
#pragma unroll
            for (int nb = 0; nb < 8; nb++) {
                uint2 kk = Kp[(nb * 8 + g) * 36 + ks * 4 + tig];
                mma_tf32(s_[nb], qhi[ks], kk.x, kk.y);
            }
        }
        __syncthreads();   // Kp fully consumed

        // refill K(t+1) into the single K buffer; lands during softmax+PV
        if (t < NT - 1) {
            const char* ksrc = gk + (size_t)(t + 1) * 2304 * 8;
#pragma unroll
            for (int i = 0; i < 9; i++) {
                int off = (tid + 128 * i) * 16;
                CP16(KPA + off, ksrc + off);
            }
            CP_COMMIT();
        }

        if (t == NT - 1) {
#pragma unroll
            for (int nb = 0; nb < 8; nb++) {
                int c = 1024 + nb * 8 + 2 * tig;
                if (c >= SEQL)     { s_[nb][0] = -INFINITY; s_[nb][2] = -INFINITY; }
                if (c + 1 >= SEQL) { s_[nb][1] = -INFINITY; s_[nb][3] = -INFINITY; }
            }
        }

        // ---- online softmax
        float rm0 = -INFINITY, rm1 = -INFINITY;
#pragma unroll
        for (int nb = 0; nb < 8; nb++) {
            rm0 = fmaxf(rm0, fmaxf(s_[nb][0], s_[nb][1]));
            rm1 = fmaxf(rm1, fmaxf(s_[nb][2], s_[nb][3]));
        }
        rm0 = fmaxf(rm0, __shfl_xor_sync(0xffffffffu, rm0, 1));
        rm0 = fmaxf(rm0, __shfl_xor_sync(0xffffffffu, rm0, 2));
        rm1 = fmaxf(rm1, __shfl_xor_sync(0xffffffffu, rm1, 1));
        rm1 = fmaxf(rm1, __shfl_xor_sync(0xffffffffu, rm1, 2));
        float nm0 = fmaxf(m0, rm0), nm1 = fmaxf(m1, rm1);
        float corr0 = __expf(m0 - nm0), corr1 = __expf(m1 - nm1);
        m0 = nm0; m1 = nm1;

        float rs0 = 0.f, rs1 = 0.f;
#pragma unroll
        for (int nb = 0; nb < 8; nb++) {
            s_[nb][0] = __expf(s_[nb][0] - m0);
            s_[nb][1] = __expf(s_[nb][1] - m0);
            s_[nb][2] = __expf(s_[nb][2] - m1);
            s_[nb][3] = __expf(s_[nb][3] - m1);
            rs0 += s_[nb][0] + s_[nb][1];
            rs1 += s_[nb][2] + s_[nb][3];
        }
        rs0 += __shfl_xor_sync(0xffffffffu, rs0, 1);
        rs0 += __shfl_xor_sync(0xffffffffu, rs0, 2);
        rs1 += __shfl_xor_sync(0xffffffffu, rs1, 1);
        rs1 += __shfl_xor_sync(0xffffffffu, rs1, 2);
        l0 = l0 * corr0 + rs0;
        l1 = l1 * corr1 + rs1;

#pragma unroll
        for (int nb = 0; nb < 8; nb++) {
            o[nb][0] *= corr0; o[nb][1] *= corr0;
            o[nb][2] *= corr1; o[nb][3] *= corr1;
        }

        // ---- P to SMEM (own warp's rows only)
#pragma unroll
        for (int nb = 0; nb < 8; nb++) {
            *(float2*)(Ps + (wrow + g) * 68 + nb * 8 + 2 * tig)     = make_float2(s_[nb][0], s_[nb][1]);
            *(float2*)(Ps + (wrow + g + 8) * 68 + nb * 8 + 2 * tig) = make_float2(s_[nb][2], s_[nb][3]);
        }
        __syncwarp();

        // ---- O += P V
        uint32_t* Vs = (uint32_t*)(sm + ((t & 1) ? V1_OFF : V0_OFF));
#pragma unroll
        for (int ks = 0; ks < 8; ks++) {
            uint32_t pa[4];
            pa[0] = f2tf32(Ps[(wrow + g) * 68 + 8 * ks + tig]);
            pa[1] = f2tf32(Ps[(wrow + g + 8) * 68 + 8 * ks + tig]);
            pa[2] = f2tf32(Ps[(wrow + g) * 68 + 8 * ks + tig + 4]);
            pa[3] = f2tf32(Ps[(wrow + g + 8) * 68 + 8 * ks + tig + 4]);
#pragma unroll
            for (int nb = 0; nb < 8; nb++) {
                int r0 = 8 * ks + tig;
                int cc = nb * 8 + g;
                mma_tf32(o[nb], pa, Vs[r0 * 72 + cc], Vs[(r0 + 4) * 72 + cc]);
            }
        }
        // no trailing barrier: next tile's top barrier protects buffers
    }

    // ---- normalize + store
    float inv0 = 1.0f / l0, inv1 = 1.0f / l1;
    int b = bh / HDS, h = bh % HDS;
    int s0 = qb * 64 + wrow + g;
    int s1 = s0 + 8;
#pragma unroll
    for (int nb = 0; nb < 8; nb++) {
        int cc = nb * 8 + 2 * tig;
        if (s0 < SEQL) {
            float* dst = g_ao + ((size_t)b * SEQL + s0) * EMB + h * HD + cc;
            *(float2*)dst = make_float2(o[nb][0] * inv0, o[nb][1] * inv0);
        }
        if (s1 < SEQL) {
            float* dst = g_ao + ((size_t)b * SEQL + s1) * EMB + h * HD + cc;
            *(float2*)dst = make_float2(o[nb][2] * inv1, o[nb][3] * inv1);
        }
    }
}

// ===================== launch =====================
extern "C" void kernel_launch(void* const* d_in, const int* in_sizes, int n_in,
                              void* d_out, int out_size)
{
    const float* x  = (const float*)d_in[0];
    const float* Wq = (const float*)d_in[1];
    const float* Wk = (const float*)d_in[2];
    const float* Wv = (const float*)d_in[3];
    const float* Wo = (const float*)d_in[4];
    const float* bo = (const float*)d_in[5];
    float* out = (float*)d_out;

    double xg = 2.0;
    for (int it = 0; it < 10; ++it) xg = pow(1.0 + xg, 1.0 / 3.0);
    float inv_g = (float)(1.0 / xg);

    cudaFuncSetAttribute(attn_mma_kernel,
                         cudaFuncAttributeMaxDynamicSharedMemorySize, ATTN_SMEM);
    cudaFuncSetAttribute(qkv_mma_kernel,
                         cudaFuncAttributeMaxDynamicSharedMemorySize, GEMM_SMEM);
    cudaFuncSetAttribute(proj_mma_kernel,
                         cudaFuncAttributeMaxDynamicSharedMemorySize, GEMM_SMEM);

    init_freqs<<<1, 192>>>(inv_g);
    init_trig<<<(SEQL * HDS * NF + 255) / 256, 256>>>();

    dim3 qkv_grid((ROWS + 127) / 128, HDS, 3);
    qkv_mma_kernel<<<qkv_grid, 256, GEMM_SMEM>>>(x, Wq, Wk, Wv);

    pack_k_kernel<<<(BHN * NPAD * 8 + 255) / 256, 256>>>();
    pack_v_kernel<<<(BHN * NPAD * 18 + 255) / 256, 256>>>();

    dim3 attn_grid(NT, BHN);
    attn_mma_kernel<<<attn_grid, 128, ATTN_SMEM>>>();

    dim3 proj_grid((ROWS + 127) / 128, EMB / 64);
    proj_mma_kernel<<<proj_grid, 256, GEMM_SMEM>>>(Wo, bo, out);
}